// round 4
// baseline (speedup 1.0000x reference)
#include <cuda_runtime.h>
#include <math.h>

// Problem constants
#define BB     2
#define SS     2048
#define DMODEL 2048
#define LAT    512
#define NHD    16
#define HD     128
#define PHD    64
#define DQK    192     // HD + PHD
#define MROWS  4096    // BB * SS

// ---------------- scratch (static device globals; no allocation) ----------
__device__ float g_latent[MROWS * (3 * LAT)];   // [4096,1536]
__device__ float g_qmain [MROWS * DMODEL];      // [4096,2048]
__device__ float g_kmain [MROWS * DMODEL];
__device__ float g_vmain [MROWS * DMODEL];
__device__ float g_posq  [MROWS * (NHD * PHD)]; // [4096,1024]
__device__ float g_posk  [MROWS * PHD];         // [4096,64]
__device__ float g_attn  [MROWS * DMODEL];      // [b,s,h,d] packed

// ======================= generic SGEMM + bias ==============================
// C[m, n] = sum_k A[m*lda + aoff + k] * W[k*ldw + n] + bias[n]
// Tile 128x128x8, 256 threads, 8x8 per thread. M = gridDim.y*128 (always
// divisible). K % 8 == 0 always. N handled with chunk guards (N % 8 == 0).
__global__ __launch_bounds__(256, 2)
void sgemm_bias(const float* __restrict__ A, int lda, int aoff,
                const float* __restrict__ W, int ldw,
                const float* __restrict__ bias,
                float* __restrict__ C, int ldc,
                int N, int K)
{
    __shared__ float As[8][128];   // transposed A tile
    __shared__ float Bs[8][128];

    const int tid  = threadIdx.x;
    const int m0   = blockIdx.y * 128;
    const int n0   = blockIdx.x * 128;

    const int arow = tid >> 1;          // 0..127
    const int acol = (tid & 1) * 4;     // 0 or 4
    const int brow = tid >> 5;          // 0..7
    const int bcol = (tid & 31) * 4;    // 0..124

    const int tx = tid & 15;
    const int ty = tid >> 4;

    float acc[8][8];
#pragma unroll
    for (int i = 0; i < 8; i++)
#pragma unroll
        for (int j = 0; j < 8; j++) acc[i][j] = 0.0f;

    const float* Aptr = A + (long)(m0 + arow) * lda + aoff + acol;
    const float* Wptr = W + (long)brow * ldw + n0 + bcol;
    const bool bvalid = (n0 + bcol) < N;

    for (int kt = 0; kt < K; kt += 8) {
        float4 a = *(const float4*)(Aptr + kt);
        As[acol + 0][arow] = a.x;
        As[acol + 1][arow] = a.y;
        As[acol + 2][arow] = a.z;
        As[acol + 3][arow] = a.w;

        float4 b = bvalid ? *(const float4*)(Wptr + (long)kt * ldw)
                          : make_float4(0.f, 0.f, 0.f, 0.f);
        *(float4*)&Bs[brow][bcol] = b;
        __syncthreads();

#pragma unroll
        for (int k = 0; k < 8; k++) {
            float4 a0 = *(const float4*)&As[k][ty * 8];
            float4 a1 = *(const float4*)&As[k][ty * 8 + 4];
            float4 b0 = *(const float4*)&Bs[k][tx * 8];
            float4 b1 = *(const float4*)&Bs[k][tx * 8 + 4];
            float ar[8] = {a0.x, a0.y, a0.z, a0.w, a1.x, a1.y, a1.z, a1.w};
            float br[8] = {b0.x, b0.y, b0.z, b0.w, b1.x, b1.y, b1.z, b1.w};
#pragma unroll
            for (int i = 0; i < 8; i++)
#pragma unroll
                for (int j = 0; j < 8; j++)
                    acc[i][j] = fmaf(ar[i], br[j], acc[i][j]);
        }
        __syncthreads();
    }

    const int ncol = n0 + tx * 8;
    if (ncol < N) {
        float4 bb0 = *(const float4*)&bias[ncol];
        float4 bb1 = *(const float4*)&bias[ncol + 4];
#pragma unroll
        for (int i = 0; i < 8; i++) {
            long m = m0 + ty * 8 + i;
            float4 o0 = make_float4(acc[i][0] + bb0.x, acc[i][1] + bb0.y,
                                    acc[i][2] + bb0.z, acc[i][3] + bb0.w);
            float4 o1 = make_float4(acc[i][4] + bb1.x, acc[i][5] + bb1.y,
                                    acc[i][6] + bb1.z, acc[i][7] + bb1.w);
            *(float4*)&C[m * ldc + ncol]     = o0;
            *(float4*)&C[m * ldc + ncol + 4] = o1;
        }
    }
}

// ======================= RoPE kernels ======================================
// inv_freq[i] = 50000^(-i/32) = 2^(-i * log2(50000)/32)
#define LOG2_THETA_OVER_32 0.48780126482613787f

__global__ void rope_q_kernel(float* __restrict__ p)  // [4096][16*64], in place
{
    int idx = blockIdx.x * 256 + threadIdx.x;
    if (idx >= MROWS * 512) return;
    int r   = idx >> 9;
    int rem = idx & 511;
    int h   = rem >> 5;
    int i   = rem & 31;
    int s   = r & (SS - 1);

    float invf = exp2f(-(float)i * LOG2_THETA_OVER_32);
    float ang  = (float)s * invf;
    float sn, cs;
    sincosf(ang, &sn, &cs);

    float* base = p + (long)r * (NHD * PHD) + h * PHD + i;
    float x0 = base[0], x1 = base[32];
    base[0]  = x0 * cs - x1 * sn;
    base[32] = x1 * cs + x0 * sn;
}

__global__ void rope_k_kernel(float* __restrict__ p)  // [4096][64], in place
{
    int idx = blockIdx.x * 256 + threadIdx.x;
    if (idx >= MROWS * 32) return;
    int r = idx >> 5;
    int i = idx & 31;
    int s = r & (SS - 1);

    float invf = exp2f(-(float)i * LOG2_THETA_OVER_32);
    float ang  = (float)s * invf;
    float sn, cs;
    sincosf(ang, &sn, &cs);

    float* base = p + (long)r * PHD + i;
    float x0 = base[0], x1 = base[32];
    base[0]  = x0 * cs - x1 * sn;
    base[32] = x1 * cs + x0 * sn;
}

// ======================= flash attention ===================================
// grid = (32 q-tiles, 32 batch*head). block = 256 (ty 0..15 rows, tx 0..15).
// Each thread: 4 q-rows (r0..r0+3), score cols {tx,tx+16,tx+32,tx+48},
// output cols d = tx*8..tx*8+7.
#define QPAD 196
#define KPAD 196
#define PPAD 76
#define ATTN_SMEM_FLOATS (64 * QPAD + 64 * KPAD + 64 * 128 + 64 * PPAD)
#define ATTN_SMEM_BYTES  (ATTN_SMEM_FLOATS * 4)

__global__ __launch_bounds__(256, 1)
void attn_kernel(const float* __restrict__ qmain, const float* __restrict__ posq,
                 const float* __restrict__ kmain, const float* __restrict__ posk,
                 const float* __restrict__ vmain, float* __restrict__ outp)
{
    extern __shared__ float sm[];
    float* Qs = sm;                   // [64][QPAD]
    float* Ks = Qs + 64 * QPAD;       // [64][KPAD]
    float* Vs = Ks + 64 * KPAD;       // [64][128]
    float* Ps = Vs + 64 * 128;        // [64][PPAD]

    const int bh = blockIdx.y;
    const int b  = bh >> 4;
    const int h  = bh & 15;
    const int qt = (int)gridDim.x - 1 - (int)blockIdx.x;  // heavy tiles first
    const int m0 = qt * 64;

    const int tid = threadIdx.x;
    const int tx  = tid & 15;
    const int ty  = tid >> 4;
    const int r0  = ty * 4;

    const long rowbase = (long)b * SS;
    const float scale = 0.07216878364870323f;  // 1/sqrt(192)

    // ---- load Q tile (once per block) ----
    for (int idx = tid; idx < 64 * DQK; idx += 256) {
        int m = idx / DQK, d = idx % DQK;
        float v;
        if (d < HD) v = qmain[(rowbase + m0 + m) * DMODEL + h * HD + d];
        else        v = posq [(rowbase + m0 + m) * (NHD * PHD) + h * PHD + (d - HD)];
        Qs[m * QPAD + d] = v;
    }

    float mi[4], li[4], acc[4][8];
#pragma unroll
    for (int i = 0; i < 4; i++) {
        mi[i] = -1e30f;
        li[i] = 0.0f;
#pragma unroll
        for (int j = 0; j < 8; j++) acc[i][j] = 0.0f;
    }
    __syncthreads();

    for (int t = 0; t <= qt; ++t) {
        const int n0 = t * 64;

        // ---- load K, V tiles ----
        for (int idx = tid; idx < 64 * DQK; idx += 256) {
            int n = idx / DQK, d = idx % DQK;
            float v;
            if (d < HD) v = kmain[(rowbase + n0 + n) * DMODEL + h * HD + d];
            else        v = posk [(rowbase + n0 + n) * PHD + (d - HD)];
            Ks[n * KPAD + d] = v;
        }
        for (int idx = tid; idx < 64 * HD; idx += 256) {
            int n = idx >> 7, d = idx & 127;
            Vs[idx] = vmain[(rowbase + n0 + n) * DMODEL + h * HD + d];
        }
        __syncthreads();

        // ---- scores: 4x4 per thread over DQK=192 ----
        float sc[4][4];
#pragma unroll
        for (int i = 0; i < 4; i++)
#pragma unroll
            for (int j = 0; j < 4; j++) sc[i][j] = 0.0f;

#pragma unroll 2
        for (int k4 = 0; k4 < DQK; k4 += 4) {
            float4 qv[4], kv[4];
#pragma unroll
            for (int i = 0; i < 4; i++)
                qv[i] = *(const float4*)&Qs[(r0 + i) * QPAD + k4];
#pragma unroll
            for (int j = 0; j < 4; j++)
                kv[j] = *(const float4*)&Ks[(tx + 16 * j) * KPAD + k4];
#pragma unroll
            for (int i = 0; i < 4; i++)
#pragma unroll
                for (int j = 0; j < 4; j++) {
                    sc[i][j] = fmaf(qv[i].x, kv[j].x, sc[i][j]);
                    sc[i][j] = fmaf(qv[i].y, kv[j].y, sc[i][j]);
                    sc[i][j] = fmaf(qv[i].z, kv[j].z, sc[i][j]);
                    sc[i][j] = fmaf(qv[i].w, kv[j].w, sc[i][j]);
                }
        }

        // scale + causal mask (mask only possible on the diagonal tile)
        const bool diag = (t == qt);
#pragma unroll
        for (int i = 0; i < 4; i++)
#pragma unroll
            for (int j = 0; j < 4; j++) {
                sc[i][j] *= scale;
                if (diag) {
                    int nq = n0 + tx + 16 * j;
                    int mq = m0 + r0 + i;
                    if (nq > mq) sc[i][j] = -1e30f;
                }
            }

        // ---- online softmax update (per row, reduced across 16 tx lanes) --
#pragma unroll
        for (int i = 0; i < 4; i++) {
            float tmax = fmaxf(fmaxf(sc[i][0], sc[i][1]), fmaxf(sc[i][2], sc[i][3]));
#pragma unroll
            for (int off = 8; off >= 1; off >>= 1)
                tmax = fmaxf(tmax, __shfl_xor_sync(0xffffffffu, tmax, off));

            float mnew  = fmaxf(mi[i], tmax);
            float alpha = __expf(mi[i] - mnew);

            float ps0 = __expf(sc[i][0] - mnew);
            float ps1 = __expf(sc[i][1] - mnew);
            float ps2 = __expf(sc[i][2] - mnew);
            float ps3 = __expf(sc[i][3] - mnew);
            float rsum = ps0 + ps1 + ps2 + ps3;
#pragma unroll
            for (int off = 8; off >= 1; off >>= 1)
                rsum += __shfl_xor_sync(0xffffffffu, rsum, off);

            li[i] = li[i] * alpha + rsum;
            mi[i] = mnew;
#pragma unroll
            for (int d = 0; d < 8; d++) acc[i][d] *= alpha;

            Ps[(r0 + i) * PPAD + tx]      = ps0;
            Ps[(r0 + i) * PPAD + tx + 16] = ps1;
            Ps[(r0 + i) * PPAD + tx + 32] = ps2;
            Ps[(r0 + i) * PPAD + tx + 48] = ps3;
        }
        __syncthreads();

        // ---- P @ V : each thread 4 rows x 8 d-cols ----
#pragma unroll 2
        for (int n = 0; n < 64; n++) {
            float4 v0 = *(const float4*)&Vs[n * 128 + tx * 8];
            float4 v1 = *(const float4*)&Vs[n * 128 + tx * 8 + 4];
#pragma unroll
            for (int i = 0; i < 4; i++) {
                float p = Ps[(r0 + i) * PPAD + n];
                acc[i][0] = fmaf(p, v0.x, acc[i][0]);
                acc[i][1] = fmaf(p, v0.y, acc[i][1]);
                acc[i][2] = fmaf(p, v0.z, acc[i][2]);
                acc[i][3] = fmaf(p, v0.w, acc[i][3]);
                acc[i][4] = fmaf(p, v1.x, acc[i][4]);
                acc[i][5] = fmaf(p, v1.y, acc[i][5]);
                acc[i][6] = fmaf(p, v1.z, acc[i][6]);
                acc[i][7] = fmaf(p, v1.w, acc[i][7]);
            }
        }
        __syncthreads();
    }

    // ---- write O, packed as [b, s, h, d] ----
#pragma unroll
    for (int i = 0; i < 4; i++) {
        float inv = 1.0f / li[i];
        long row = rowbase + m0 + r0 + i;
        float4 o0 = make_float4(acc[i][0] * inv, acc[i][1] * inv,
                                acc[i][2] * inv, acc[i][3] * inv);
        float4 o1 = make_float4(acc[i][4] * inv, acc[i][5] * inv,
                                acc[i][6] * inv, acc[i][7] * inv);
        *(float4*)&outp[row * DMODEL + h * HD + tx * 8]     = o0;
        *(float4*)&outp[row * DMODEL + h * HD + tx * 8 + 4] = o1;
    }
}

// ======================= launch ============================================
extern "C" void kernel_launch(void* const* d_in, const int* in_sizes, int n_in,
                              void* d_out, int out_size)
{
    const float* x      = (const float*)d_in[0];
    const float* w_qkv  = (const float*)d_in[1];
    const float* b_qkv  = (const float*)d_in[2];
    const float* w_qup  = (const float*)d_in[3];
    const float* b_qup  = (const float*)d_in[4];
    const float* w_kup  = (const float*)d_in[5];
    const float* b_kup  = (const float*)d_in[6];
    const float* w_vup  = (const float*)d_in[7];
    const float* b_vup  = (const float*)d_in[8];
    const float* w_qpos = (const float*)d_in[9];
    const float* b_qpos = (const float*)d_in[10];
    const float* w_kpos = (const float*)d_in[11];
    const float* b_kpos = (const float*)d_in[12];
    const float* w_o    = (const float*)d_in[13];
    const float* b_o    = (const float*)d_in[14];
    float* out = (float*)d_out;

    float *latent, *qmain, *kmain, *vmain, *posq, *posk, *attnb;
    cudaGetSymbolAddress((void**)&latent, g_latent);
    cudaGetSymbolAddress((void**)&qmain,  g_qmain);
    cudaGetSymbolAddress((void**)&kmain,  g_kmain);
    cudaGetSymbolAddress((void**)&vmain,  g_vmain);
    cudaGetSymbolAddress((void**)&posq,   g_posq);
    cudaGetSymbolAddress((void**)&posk,   g_posk);
    cudaGetSymbolAddress((void**)&attnb,  g_attn);

    cudaFuncSetAttribute(attn_kernel,
                         cudaFuncAttributeMaxDynamicSharedMemorySize,
                         ATTN_SMEM_BYTES);

    dim3 blk(256);
    const int MG = MROWS / 128;  // 32 grid rows

    // latent_qkv = x @ w_qkv + b_qkv                [4096,1536]
    sgemm_bias<<<dim3(1536 / 128, MG), blk>>>(x, DMODEL, 0, w_qkv, 3 * LAT,
                                              b_qkv, latent, 3 * LAT,
                                              3 * LAT, DMODEL);
    // pos_k raw = x @ w_kpos + b_kpos               [4096,64]
    sgemm_bias<<<dim3(1, MG), blk>>>(x, DMODEL, 0, w_kpos, PHD,
                                     b_kpos, posk, PHD, PHD, DMODEL);
    // q_main = lq @ w_qup + b_qup                   [4096,2048]
    sgemm_bias<<<dim3(DMODEL / 128, MG), blk>>>(latent, 3 * LAT, 0, w_qup, DMODEL,
                                                b_qup, qmain, DMODEL, DMODEL, LAT);
    // k_main = lk @ w_kup + b_kup
    sgemm_bias<<<dim3(DMODEL / 128, MG), blk>>>(latent, 3 * LAT, LAT, w_kup, DMODEL,
                                                b_kup, kmain, DMODEL, DMODEL, LAT);
    // v_main = lv @ w_vup + b_vup
    sgemm_bias<<<dim3(DMODEL / 128, MG), blk>>>(latent, 3 * LAT, 2 * LAT, w_vup, DMODEL,
                                                b_vup, vmain, DMODEL, DMODEL, LAT);
    // pos_q raw = lq @ w_qpos + b_qpos              [4096,1024]
    sgemm_bias<<<dim3(1024 / 128, MG), blk>>>(latent, 3 * LAT, 0, w_qpos, NHD * PHD,
                                              b_qpos, posq, NHD * PHD, NHD * PHD, LAT);

    // RoPE (in place)
    rope_q_kernel<<<(MROWS * 512) / 256, 256>>>(posq);
    rope_k_kernel<<<(MROWS * 32) / 256, 256>>>(posk);

    // attention -> attnb packed [b, s, h, d]
    attn_kernel<<<dim3(SS / 64, BB * NHD), blk, ATTN_SMEM_BYTES>>>(
        qmain, posq, kmain, posk, vmain, attnb);

    // out = attnb @ w_o + b_o                       [4096,2048]
    sgemm_bias<<<dim3(DMODEL / 128, MG), blk>>>(attnb, DMODEL, 0, w_o, DMODEL,
                                                b_o, out, DMODEL, DMODEL, DMODEL);
}

// round 5
// speedup vs baseline: 1.0275x; 1.0275x over previous
#include <cuda_runtime.h>
#include <math.h>

// Problem constants
#define BB     2
#define SS     2048
#define DMODEL 2048
#define LAT    512
#define NHD    16
#define HD     128
#define PHD    64
#define DQK    192     // HD + PHD
#define MROWS  4096    // BB * SS

// ---------------- scratch (static device globals; no allocation) ----------
__device__ float g_latent[MROWS * (3 * LAT)];   // [4096,1536]
__device__ float g_qmain [MROWS * DMODEL];      // [4096,2048]
__device__ float g_kmain [MROWS * DMODEL];
__device__ float g_vmain [MROWS * DMODEL];
__device__ float g_posq  [MROWS * (NHD * PHD)]; // [4096,1024]
__device__ float g_posk  [MROWS * PHD];         // [4096,64]
__device__ float g_attn  [MROWS * DMODEL];      // [b,s,h,d] packed

// ======================= generic SGEMM + bias ==============================
// C[m, n] = sum_k A[m*lda + aoff + k] * W[k*ldw + n] + bias[n]
// Tile 128x128x8, 256 threads, 8x8 per thread. M = gridDim.y*128 (always
// divisible). K % 8 == 0 always. N handled with chunk guards (N % 8 == 0).
__global__ __launch_bounds__(256, 2)
void sgemm_bias(const float* __restrict__ A, int lda, int aoff,
                const float* __restrict__ W, int ldw,
                const float* __restrict__ bias,
                float* __restrict__ C, int ldc,
                int N, int K)
{
    __shared__ float As[8][128];   // transposed A tile
    __shared__ float Bs[8][128];

    const int tid  = threadIdx.x;
    const int m0   = blockIdx.y * 128;
    const int n0   = blockIdx.x * 128;

    const int arow = tid >> 1;          // 0..127
    const int acol = (tid & 1) * 4;     // 0 or 4
    const int brow = tid >> 5;          // 0..7
    const int bcol = (tid & 31) * 4;    // 0..124

    const int tx = tid & 15;
    const int ty = tid >> 4;

    float acc[8][8];
#pragma unroll
    for (int i = 0; i < 8; i++)
#pragma unroll
        for (int j = 0; j < 8; j++) acc[i][j] = 0.0f;

    const float* Aptr = A + (long)(m0 + arow) * lda + aoff + acol;
    const float* Wptr = W + (long)brow * ldw + n0 + bcol;
    const bool bvalid = (n0 + bcol) < N;

    for (int kt = 0; kt < K; kt += 8) {
        float4 a = *(const float4*)(Aptr + kt);
        As[acol + 0][arow] = a.x;
        As[acol + 1][arow] = a.y;
        As[acol + 2][arow] = a.z;
        As[acol + 3][arow] = a.w;

        float4 b = bvalid ? *(const float4*)(Wptr + (long)kt * ldw)
                          : make_float4(0.f, 0.f, 0.f, 0.f);
        *(float4*)&Bs[brow][bcol] = b;
        __syncthreads();

#pragma unroll
        for (int k = 0; k < 8; k++) {
            float4 a0 = *(const float4*)&As[k][ty * 8];
            float4 a1 = *(const float4*)&As[k][ty * 8 + 4];
            float4 b0 = *(const float4*)&Bs[k][tx * 8];
            float4 b1 = *(const float4*)&Bs[k][tx * 8 + 4];
            float ar[8] = {a0.x, a0.y, a0.z, a0.w, a1.x, a1.y, a1.z, a1.w};
            float br[8] = {b0.x, b0.y, b0.z, b0.w, b1.x, b1.y, b1.z, b1.w};
#pragma unroll
            for (int i = 0; i < 8; i++)
#pragma unroll
                for (int j = 0; j < 8; j++)
                    acc[i][j] = fmaf(ar[i], br[j], acc[i][j]);
        }
        __syncthreads();
    }

    const int ncol = n0 + tx * 8;
    if (ncol < N) {
        float4 bb0 = *(const float4*)&bias[ncol];
        float4 bb1 = *(const float4*)&bias[ncol + 4];
#pragma unroll
        for (int i = 0; i < 8; i++) {
            long m = m0 + ty * 8 + i;
            float4 o0 = make_float4(acc[i][0] + bb0.x, acc[i][1] + bb0.y,
                                    acc[i][2] + bb0.z, acc[i][3] + bb0.w);
            float4 o1 = make_float4(acc[i][4] + bb1.x, acc[i][5] + bb1.y,
                                    acc[i][6] + bb1.z, acc[i][7] + bb1.w);
            *(float4*)&C[m * ldc + ncol]     = o0;
            *(float4*)&C[m * ldc + ncol + 4] = o1;
        }
    }
}

// ======================= RoPE kernels ======================================
// inv_freq[i] = 50000^(-i/32) = 2^(-i * log2(50000)/32)
#define LOG2_THETA_OVER_32 0.48780126482613787f

__global__ void rope_q_kernel(float* __restrict__ p)  // [4096][16*64], in place
{
    int idx = blockIdx.x * 256 + threadIdx.x;
    if (idx >= MROWS * 512) return;
    int r   = idx >> 9;
    int rem = idx & 511;
    int h   = rem >> 5;
    int i   = rem & 31;
    int s   = r & (SS - 1);

    float invf = exp2f(-(float)i * LOG2_THETA_OVER_32);
    float ang  = (float)s * invf;
    float sn, cs;
    sincosf(ang, &sn, &cs);

    float* base = p + (long)r * (NHD * PHD) + h * PHD + i;
    float x0 = base[0], x1 = base[32];
    base[0]  = x0 * cs - x1 * sn;
    base[32] = x1 * cs + x0 * sn;
}

__global__ void rope_k_kernel(float* __restrict__ p)  // [4096][64], in place
{
    int idx = blockIdx.x * 256 + threadIdx.x;
    if (idx >= MROWS * 32) return;
    int r = idx >> 5;
    int i = idx & 31;
    int s = r & (SS - 1);

    float invf = exp2f(-(float)i * LOG2_THETA_OVER_32);
    float ang  = (float)s * invf;
    float sn, cs;
    sincosf(ang, &sn, &cs);

    float* base = p + (long)r * PHD + i;
    float x0 = base[0], x1 = base[32];
    base[0]  = x0 * cs - x1 * sn;
    base[32] = x1 * cs + x0 * sn;
}

// ======================= flash attention ===================================
// grid = (32 q-tiles, 32 batch*head). block = 256 (ty 0..15 rows, tx 0..15).
// Each thread: 4 q-rows (r0..r0+3), score cols {tx,tx+16,tx+32,tx+48},
// output cols d = tx*8..tx*8+7.
#define QPAD 196
#define KPAD 196
#define PPAD 76
#define ATTN_SMEM_FLOATS (64 * QPAD + 64 * KPAD + 64 * 128 + 64 * PPAD)
#define ATTN_SMEM_BYTES  (ATTN_SMEM_FLOATS * 4)

__global__ __launch_bounds__(256, 1)
void attn_kernel(const float* __restrict__ qmain, const float* __restrict__ posq,
                 const float* __restrict__ kmain, const float* __restrict__ posk,
                 const float* __restrict__ vmain, float* __restrict__ outp)
{
    extern __shared__ float sm[];
    float* Qs = sm;                   // [64][QPAD]
    float* Ks = Qs + 64 * QPAD;       // [64][KPAD]
    float* Vs = Ks + 64 * KPAD;       // [64][128]
    float* Ps = Vs + 64 * 128;        // [64][PPAD]

    const int bh = blockIdx.y;
    const int b  = bh >> 4;
    const int h  = bh & 15;
    const int qt = (int)gridDim.x - 1 - (int)blockIdx.x;  // heavy tiles first
    const int m0 = qt * 64;

    const int tid = threadIdx.x;
    const int tx  = tid & 15;
    const int ty  = tid >> 4;
    const int r0  = ty * 4;

    const long rowbase = (long)b * SS;
    const float scale = 0.07216878364870323f;  // 1/sqrt(192)

    // ---- load Q tile (once per block) ----
    for (int idx = tid; idx < 64 * DQK; idx += 256) {
        int m = idx / DQK, d = idx % DQK;
        float v;
        if (d < HD) v = qmain[(rowbase + m0 + m) * DMODEL + h * HD + d];
        else        v = posq [(rowbase + m0 + m) * (NHD * PHD) + h * PHD + (d - HD)];
        Qs[m * QPAD + d] = v;
    }

    float mi[4], li[4], acc[4][8];
#pragma unroll
    for (int i = 0; i < 4; i++) {
        mi[i] = -1e30f;
        li[i] = 0.0f;
#pragma unroll
        for (int j = 0; j < 8; j++) acc[i][j] = 0.0f;
    }
    __syncthreads();

    for (int t = 0; t <= qt; ++t) {
        const int n0 = t * 64;

        // ---- load K, V tiles ----
        for (int idx = tid; idx < 64 * DQK; idx += 256) {
            int n = idx / DQK, d = idx % DQK;
            float v;
            if (d < HD) v = kmain[(rowbase + n0 + n) * DMODEL + h * HD + d];
            else        v = posk [(rowbase + n0 + n) * PHD + (d - HD)];
            Ks[n * KPAD + d] = v;
        }
        for (int idx = tid; idx < 64 * HD; idx += 256) {
            int n = idx >> 7, d = idx & 127;
            Vs[idx] = vmain[(rowbase + n0 + n) * DMODEL + h * HD + d];
        }
        __syncthreads();

        // ---- scores: 4x4 per thread over DQK=192 ----
        float sc[4][4];
#pragma unroll
        for (int i = 0; i < 4; i++)
#pragma unroll
            for (int j = 0; j < 4; j++) sc[i][j] = 0.0f;

#pragma unroll 2
        for (int k4 = 0; k4 < DQK; k4 += 4) {
            float4 qv[4], kv[4];
#pragma unroll
            for (int i = 0; i < 4; i++)
                qv[i] = *(const float4*)&Qs[(r0 + i) * QPAD + k4];
#pragma unroll
            for (int j = 0; j < 4; j++)
                kv[j] = *(const float4*)&Ks[(tx + 16 * j) * KPAD + k4];
#pragma unroll
            for (int i = 0; i < 4; i++)
#pragma unroll
                for (int j = 0; j < 4; j++) {
                    sc[i][j] = fmaf(qv[i].x, kv[j].x, sc[i][j]);
                    sc[i][j] = fmaf(qv[i].y, kv[j].y, sc[i][j]);
                    sc[i][j] = fmaf(qv[i].z, kv[j].z, sc[i][j]);
                    sc[i][j] = fmaf(qv[i].w, kv[j].w, sc[i][j]);
                }
        }

        // scale + causal mask (mask only possible on the diagonal tile)
        const bool diag = (t == qt);
#pragma unroll
        for (int i = 0; i < 4; i++)
#pragma unroll
            for (int j = 0; j < 4; j++) {
                sc[i][j] *= scale;
                if (diag) {
                    int nq = n0 + tx + 16 * j;
                    int mq = m0 + r0 + i;
                    if (nq > mq) sc[i][j] = -1e30f;
                }
            }

        // ---- online softmax update (per row, reduced across 16 tx lanes) --
#pragma unroll
        for (int i = 0; i < 4; i++) {
            float tmax = fmaxf(fmaxf(sc[i][0], sc[i][1]), fmaxf(sc[i][2], sc[i][3]));
#pragma unroll
            for (int off = 8; off >= 1; off >>= 1)
                tmax = fmaxf(tmax, __shfl_xor_sync(0xffffffffu, tmax, off));

            float mnew  = fmaxf(mi[i], tmax);
            float alpha = __expf(mi[i] - mnew);

            float ps0 = __expf(sc[i][0] - mnew);
            float ps1 = __expf(sc[i][1] - mnew);
            float ps2 = __expf(sc[i][2] - mnew);
            float ps3 = __expf(sc[i][3] - mnew);
            float rsum = ps0 + ps1 + ps2 + ps3;
#pragma unroll
            for (int off = 8; off >= 1; off >>= 1)
                rsum += __shfl_xor_sync(0xffffffffu, rsum, off);

            li[i] = li[i] * alpha + rsum;
            mi[i] = mnew;
#pragma unroll
            for (int d = 0; d < 8; d++) acc[i][d] *= alpha;

            Ps[(r0 + i) * PPAD + tx]      = ps0;
            Ps[(r0 + i) * PPAD + tx + 16] = ps1;
            Ps[(r0 + i) * PPAD + tx + 32] = ps2;
            Ps[(r0 + i) * PPAD + tx + 48] = ps3;
        }
        __syncthreads();

        // ---- P @ V : each thread 4 rows x 8 d-cols ----
#pragma unroll 2
        for (int n = 0; n < 64; n++) {
            float4 v0 = *(const float4*)&Vs[n * 128 + tx * 8];
            float4 v1 = *(const float4*)&Vs[n * 128 + tx * 8 + 4];
#pragma unroll
            for (int i = 0; i < 4; i++) {
                float p = Ps[(r0 + i) * PPAD + n];
                acc[i][0] = fmaf(p, v0.x, acc[i][0]);
                acc[i][1] = fmaf(p, v0.y, acc[i][1]);
                acc[i][2] = fmaf(p, v0.z, acc[i][2]);
                acc[i][3] = fmaf(p, v0.w, acc[i][3]);
                acc[i][4] = fmaf(p, v1.x, acc[i][4]);
                acc[i][5] = fmaf(p, v1.y, acc[i][5]);
                acc[i][6] = fmaf(p, v1.z, acc[i][6]);
                acc[i][7] = fmaf(p, v1.w, acc[i][7]);
            }
        }
        __syncthreads();
    }

    // ---- write O, packed as [b, s, h, d] ----
#pragma unroll
    for (int i = 0; i < 4; i++) {
        float inv = 1.0f / li[i];
        long row = rowbase + m0 + r0 + i;
        float4 o0 = make_float4(acc[i][0] * inv, acc[i][1] * inv,
                                acc[i][2] * inv, acc[i][3] * inv);
        float4 o1 = make_float4(acc[i][4] * inv, acc[i][5] * inv,
                                acc[i][6] * inv, acc[i][7] * inv);
        *(float4*)&outp[row * DMODEL + h * HD + tx * 8]     = o0;
        *(float4*)&outp[row * DMODEL + h * HD + tx * 8 + 4] = o1;
    }
}

// ======================= launch ============================================
extern "C" void kernel_launch(void* const* d_in, const int* in_sizes, int n_in,
                              void* d_out, int out_size)
{
    const float* x      = (const float*)d_in[0];
    const float* w_qkv  = (const float*)d_in[1];
    const float* b_qkv  = (const float*)d_in[2];
    const float* w_qup  = (const float*)d_in[3];
    const float* b_qup  = (const float*)d_in[4];
    const float* w_kup  = (const float*)d_in[5];
    const float* b_kup  = (const float*)d_in[6];
    const float* w_vup  = (const float*)d_in[7];
    const float* b_vup  = (const float*)d_in[8];
    const float* w_qpos = (const float*)d_in[9];
    const float* b_qpos = (const float*)d_in[10];
    const float* w_kpos = (const float*)d_in[11];
    const float* b_kpos = (const float*)d_in[12];
    const float* w_o    = (const float*)d_in[13];
    const float* b_o    = (const float*)d_in[14];
    float* out = (float*)d_out;

    float *latent, *qmain, *kmain, *vmain, *posq, *posk, *attnb;
    cudaGetSymbolAddress((void**)&latent, g_latent);
    cudaGetSymbolAddress((void**)&qmain,  g_qmain);
    cudaGetSymbolAddress((void**)&kmain,  g_kmain);
    cudaGetSymbolAddress((void**)&vmain,  g_vmain);
    cudaGetSymbolAddress((void**)&posq,   g_posq);
    cudaGetSymbolAddress((void**)&posk,   g_posk);
    cudaGetSymbolAddress((void**)&attnb,  g_attn);

    cudaFuncSetAttribute(attn_kernel,
                         cudaFuncAttributeMaxDynamicSharedMemorySize,
                         ATTN_SMEM_BYTES);

    dim3 blk(256);
    const int MG = MROWS / 128;  // 32 grid rows

    // latent_qkv = x @ w_qkv + b_qkv                [4096,1536]
    sgemm_bias<<<dim3(1536 / 128, MG), blk>>>(x, DMODEL, 0, w_qkv, 3 * LAT,
                                              b_qkv, latent, 3 * LAT,
                                              3 * LAT, DMODEL);
    // pos_k raw = x @ w_kpos + b_kpos               [4096,64]
    sgemm_bias<<<dim3(1, MG), blk>>>(x, DMODEL, 0, w_kpos, PHD,
                                     b_kpos, posk, PHD, PHD, DMODEL);
    // q_main = lq @ w_qup + b_qup                   [4096,2048]
    sgemm_bias<<<dim3(DMODEL / 128, MG), blk>>>(latent, 3 * LAT, 0, w_qup, DMODEL,
                                                b_qup, qmain, DMODEL, DMODEL, LAT);
    // k_main = lk @ w_kup + b_kup
    sgemm_bias<<<dim3(DMODEL / 128, MG), blk>>>(latent, 3 * LAT, LAT, w_kup, DMODEL,
                                                b_kup, kmain, DMODEL, DMODEL, LAT);
    // v_main = lv @ w_vup + b_vup
    sgemm_bias<<<dim3(DMODEL / 128, MG), blk>>>(latent, 3 * LAT, 2 * LAT, w_vup, DMODEL,
                                                b_vup, vmain, DMODEL, DMODEL, LAT);
    // pos_q raw = lq @ w_qpos + b_qpos              [4096,1024]
    sgemm_bias<<<dim3(1024 / 128, MG), blk>>>(latent, 3 * LAT, 0, w_qpos, NHD * PHD,
                                              b_qpos, posq, NHD * PHD, NHD * PHD, LAT);

    // RoPE (in place)
    rope_q_kernel<<<(MROWS * 512) / 256, 256>>>(posq);
    rope_k_kernel<<<(MROWS * 32) / 256, 256>>>(posk);

    // attention -> attnb packed [b, s, h, d]
    attn_kernel<<<dim3(SS / 64, BB * NHD), blk, ATTN_SMEM_BYTES>>>(
        qmain, posq, kmain, posk, vmain, attnb);

    // out = attnb @ w_o + b_o                       [4096,2048]
    sgemm_bias<<<dim3(DMODEL / 128, MG), blk>>>(attnb, DMODEL, 0, w_o, DMODEL,
                                                b_o, out, DMODEL, DMODEL, DMODEL);
}

// round 6
// speedup vs baseline: 1.2703x; 1.2362x over previous
#include <cuda_runtime.h>
#include <math.h>

// Problem constants
#define BB     2
#define SS     2048
#define DMODEL 2048
#define LAT    512
#define NHD    16
#define HD     128
#define PHD    64
#define DQK    192     // HD + PHD
#define MROWS  4096    // BB * SS

// ---------------- scratch (static device globals; no allocation) ----------
__device__ float g_latent[MROWS * (3 * LAT)];   // [4096,1536]
__device__ float g_qmain [MROWS * DMODEL];      // [4096,2048]
__device__ float g_kmain [MROWS * DMODEL];
__device__ float g_vmain [MROWS * DMODEL];
__device__ float g_posq  [MROWS * (NHD * PHD)]; // [4096,1024]
__device__ float g_posk  [MROWS * PHD];         // [4096,64]
__device__ float g_attn  [MROWS * DMODEL];      // [b,s,h,d] packed

// ======================= generic SGEMM + bias ==============================
// C[m, n] = sum_k A[m*lda + aoff + k] * W[k*ldw + n] + bias[n]
// Tile 128x128x8, 256 threads, 8x8 per thread (rows {ty*4+i, 64+ty*4+i},
// cols {tx*4+j, 64+tx*4+j} -> conflict-free smem fragment reads).
// Double-buffered smem, register-staged global prefetch, 1 sync / k-tile.
// N is always a multiple of 64 here; K a multiple of 8; M of 128.
__global__ __launch_bounds__(256, 2)
void sgemm_bias(const float* __restrict__ A, int lda, int aoff,
                const float* __restrict__ W, int ldw,
                const float* __restrict__ bias,
                float* __restrict__ C, int ldc,
                int N, int K)
{
    __shared__ float As[2][8][128];   // transposed A tile
    __shared__ float Bs[2][8][128];

    const int tid  = threadIdx.x;
    const int m0   = blockIdx.y * 128;
    const int n0   = blockIdx.x * 128;

    const int arow = tid >> 1;          // 0..127
    const int acol = (tid & 1) * 4;     // 0 or 4
    const int brow = tid >> 5;          // 0..7
    const int bcol = (tid & 31) * 4;    // 0..124

    const int tx = tid & 15;
    const int ty = tid >> 4;

    float acc[8][8];
#pragma unroll
    for (int i = 0; i < 8; i++)
#pragma unroll
        for (int j = 0; j < 8; j++) acc[i][j] = 0.0f;

    const float* Aptr = A + (long)(m0 + arow) * lda + aoff + acol;
    const float* Wptr = W + (long)brow * ldw + n0 + bcol;
    const bool bvalid = (n0 + bcol) < N;

    // prologue: tile 0 -> buffer 0
    {
        float4 a = *(const float4*)(Aptr);
        float4 b = bvalid ? *(const float4*)(Wptr)
                          : make_float4(0.f, 0.f, 0.f, 0.f);
        As[0][acol + 0][arow] = a.x;
        As[0][acol + 1][arow] = a.y;
        As[0][acol + 2][arow] = a.z;
        As[0][acol + 3][arow] = a.w;
        *(float4*)&Bs[0][brow][bcol] = b;
    }
    __syncthreads();

    int nbuf = 1;
    for (int kt = 8; kt < K; kt += 8) {
        // prefetch next tile into registers
        float4 an = *(const float4*)(Aptr + kt);
        float4 bn = bvalid ? *(const float4*)(Wptr + (long)kt * ldw)
                           : make_float4(0.f, 0.f, 0.f, 0.f);

        const int cb = nbuf ^ 1;   // compute buffer
#pragma unroll
        for (int k = 0; k < 8; k++) {
            float4 a0 = *(const float4*)&As[cb][k][ty * 4];
            float4 a1 = *(const float4*)&As[cb][k][64 + ty * 4];
            float4 b0 = *(const float4*)&Bs[cb][k][tx * 4];
            float4 b1 = *(const float4*)&Bs[cb][k][64 + tx * 4];
            float ar[8] = {a0.x, a0.y, a0.z, a0.w, a1.x, a1.y, a1.z, a1.w};
            float br[8] = {b0.x, b0.y, b0.z, b0.w, b1.x, b1.y, b1.z, b1.w};
#pragma unroll
            for (int i = 0; i < 8; i++)
#pragma unroll
                for (int j = 0; j < 8; j++)
                    acc[i][j] = fmaf(ar[i], br[j], acc[i][j]);
        }

        // store prefetched tile into the other buffer
        As[nbuf][acol + 0][arow] = an.x;
        As[nbuf][acol + 1][arow] = an.y;
        As[nbuf][acol + 2][arow] = an.z;
        As[nbuf][acol + 3][arow] = an.w;
        *(float4*)&Bs[nbuf][brow][bcol] = bn;
        __syncthreads();
        nbuf ^= 1;
    }

    // final tile
    {
        const int cb = nbuf ^ 1;
#pragma unroll
        for (int k = 0; k < 8; k++) {
            float4 a0 = *(const float4*)&As[cb][k][ty * 4];
            float4 a1 = *(const float4*)&As[cb][k][64 + ty * 4];
            float4 b0 = *(const float4*)&Bs[cb][k][tx * 4];
            float4 b1 = *(const float4*)&Bs[cb][k][64 + tx * 4];
            float ar[8] = {a0.x, a0.y, a0.z, a0.w, a1.x, a1.y, a1.z, a1.w};
            float br[8] = {b0.x, b0.y, b0.z, b0.w, b1.x, b1.y, b1.z, b1.w};
#pragma unroll
            for (int i = 0; i < 8; i++)
#pragma unroll
                for (int j = 0; j < 8; j++)
                    acc[i][j] = fmaf(ar[i], br[j], acc[i][j]);
        }
    }

    // epilogue (col groups are fully valid or fully invalid: N % 64 == 0)
    const int nc0 = n0 + tx * 4;
    const int nc1 = n0 + 64 + tx * 4;
    const bool v0 = nc0 < N;
    const bool v1 = nc1 < N;
    float4 bb0 = v0 ? *(const float4*)&bias[nc0] : make_float4(0,0,0,0);
    float4 bb1 = v1 ? *(const float4*)&bias[nc1] : make_float4(0,0,0,0);

#pragma unroll
    for (int g = 0; g < 2; g++) {
#pragma unroll
        for (int i = 0; i < 4; i++) {
            long m = m0 + g * 64 + ty * 4 + i;
            const float* ac = acc[g * 4 + i];
            if (v0) {
                float4 o = make_float4(ac[0] + bb0.x, ac[1] + bb0.y,
                                       ac[2] + bb0.z, ac[3] + bb0.w);
                *(float4*)&C[m * ldc + nc0] = o;
            }
            if (v1) {
                float4 o = make_float4(ac[4] + bb1.x, ac[5] + bb1.y,
                                       ac[6] + bb1.z, ac[7] + bb1.w);
                *(float4*)&C[m * ldc + nc1] = o;
            }
        }
    }
}

// ======================= RoPE kernels ======================================
// inv_freq[i] = 50000^(-i/32) = 2^(-i * log2(50000)/32)
#define LOG2_THETA_OVER_32 0.48780126482613787f

__global__ void rope_q_kernel(float* __restrict__ p)  // [4096][16*64], in place
{
    int idx = blockIdx.x * 256 + threadIdx.x;
    if (idx >= MROWS * 512) return;
    int r   = idx >> 9;
    int rem = idx & 511;
    int h   = rem >> 5;
    int i   = rem & 31;
    int s   = r & (SS - 1);

    float invf = exp2f(-(float)i * LOG2_THETA_OVER_32);
    float ang  = (float)s * invf;
    float sn, cs;
    sincosf(ang, &sn, &cs);

    float* base = p + (long)r * (NHD * PHD) + h * PHD + i;
    float x0 = base[0], x1 = base[32];
    base[0]  = x0 * cs - x1 * sn;
    base[32] = x1 * cs + x0 * sn;
}

__global__ void rope_k_kernel(float* __restrict__ p)  // [4096][64], in place
{
    int idx = blockIdx.x * 256 + threadIdx.x;
    if (idx >= MROWS * 32) return;
    int r = idx >> 5;
    int i = idx & 31;
    int s = r & (SS - 1);

    float invf = exp2f(-(float)i * LOG2_THETA_OVER_32);
    float ang  = (float)s * invf;
    float sn, cs;
    sincosf(ang, &sn, &cs);

    float* base = p + (long)r * PHD + i;
    float x0 = base[0], x1 = base[32];
    base[0]  = x0 * cs - x1 * sn;
    base[32] = x1 * cs + x0 * sn;
}

// ======================= flash attention ===================================
// grid = (32 q-tiles, 32 batch*head). block = 512 (ty 0..31 -> 2 rows each,
// tx 0..15). Score cols {tx,tx+16,tx+32,tx+48}; output cols split
// {4tx..4tx+3} and {64+4tx..64+4tx+3} (conflict-free V reads).
#define QPAD 196
#define KPAD 196
#define PPAD 76
#define ATTN_SMEM_FLOATS (64 * QPAD + 64 * KPAD + 64 * 128 + 64 * PPAD)
#define ATTN_SMEM_BYTES  (ATTN_SMEM_FLOATS * 4)

__global__ __launch_bounds__(512, 1)
void attn_kernel(const float* __restrict__ qmain, const float* __restrict__ posq,
                 const float* __restrict__ kmain, const float* __restrict__ posk,
                 const float* __restrict__ vmain, float* __restrict__ outp)
{
    extern __shared__ float sm[];
    float* Qs = sm;                   // [64][QPAD]
    float* Ks = Qs + 64 * QPAD;       // [64][KPAD]
    float* Vs = Ks + 64 * KPAD;       // [64][128]
    float* Ps = Vs + 64 * 128;        // [64][PPAD]

    const int bh = blockIdx.y;
    const int b  = bh >> 4;
    const int h  = bh & 15;
    const int qt = (int)gridDim.x - 1 - (int)blockIdx.x;  // heavy tiles first
    const int m0 = qt * 64;

    const int tid = threadIdx.x;
    const int tx  = tid & 15;
    const int ty  = tid >> 4;
    const int r0  = ty * 2;

    const long rowbase = (long)b * SS;
    const float scale = 0.07216878364870323f;  // 1/sqrt(192)

    // ---- load Q tile (once per block) ----
    for (int idx = tid; idx < 64 * DQK; idx += 512) {
        int m = idx / DQK, d = idx % DQK;
        float v;
        if (d < HD) v = qmain[(rowbase + m0 + m) * DMODEL + h * HD + d];
        else        v = posq [(rowbase + m0 + m) * (NHD * PHD) + h * PHD + (d - HD)];
        Qs[m * QPAD + d] = v;
    }

    float mi[2], li[2], acc[2][8];
#pragma unroll
    for (int i = 0; i < 2; i++) {
        mi[i] = -1e30f;
        li[i] = 0.0f;
#pragma unroll
        for (int j = 0; j < 8; j++) acc[i][j] = 0.0f;
    }
    __syncthreads();

    for (int t = 0; t <= qt; ++t) {
        const int n0 = t * 64;

        // ---- load K, V tiles ----
        for (int idx = tid; idx < 64 * DQK; idx += 512) {
            int n = idx / DQK, d = idx % DQK;
            float v;
            if (d < HD) v = kmain[(rowbase + n0 + n) * DMODEL + h * HD + d];
            else        v = posk [(rowbase + n0 + n) * PHD + (d - HD)];
            Ks[n * KPAD + d] = v;
        }
        for (int idx = tid; idx < 64 * HD; idx += 512) {
            int n = idx >> 7, d = idx & 127;
            Vs[idx] = vmain[(rowbase + n0 + n) * DMODEL + h * HD + d];
        }
        __syncthreads();

        // ---- scores: 2 rows x 4 cols per thread over DQK=192 ----
        float sc[2][4];
#pragma unroll
        for (int i = 0; i < 2; i++)
#pragma unroll
            for (int j = 0; j < 4; j++) sc[i][j] = 0.0f;

#pragma unroll 4
        for (int k4 = 0; k4 < DQK; k4 += 4) {
            float4 qv[2], kv[4];
#pragma unroll
            for (int i = 0; i < 2; i++)
                qv[i] = *(const float4*)&Qs[(r0 + i) * QPAD + k4];
#pragma unroll
            for (int j = 0; j < 4; j++)
                kv[j] = *(const float4*)&Ks[(tx + 16 * j) * KPAD + k4];
#pragma unroll
            for (int i = 0; i < 2; i++)
#pragma unroll
                for (int j = 0; j < 4; j++) {
                    sc[i][j] = fmaf(qv[i].x, kv[j].x, sc[i][j]);
                    sc[i][j] = fmaf(qv[i].y, kv[j].y, sc[i][j]);
                    sc[i][j] = fmaf(qv[i].z, kv[j].z, sc[i][j]);
                    sc[i][j] = fmaf(qv[i].w, kv[j].w, sc[i][j]);
                }
        }

        // scale + causal mask (mask only possible on the diagonal tile)
        const bool diag = (t == qt);
#pragma unroll
        for (int i = 0; i < 2; i++)
#pragma unroll
            for (int j = 0; j < 4; j++) {
                sc[i][j] *= scale;
                if (diag) {
                    int nq = n0 + tx + 16 * j;
                    int mq = m0 + r0 + i;
                    if (nq > mq) sc[i][j] = -1e30f;
                }
            }

        // ---- online softmax update (per row, reduced across 16 tx lanes) --
#pragma unroll
        for (int i = 0; i < 2; i++) {
            float tmax = fmaxf(fmaxf(sc[i][0], sc[i][1]), fmaxf(sc[i][2], sc[i][3]));
#pragma unroll
            for (int off = 8; off >= 1; off >>= 1)
                tmax = fmaxf(tmax, __shfl_xor_sync(0xffffffffu, tmax, off));

            float mnew  = fmaxf(mi[i], tmax);
            float alpha = __expf(mi[i] - mnew);

            float ps0 = __expf(sc[i][0] - mnew);
            float ps1 = __expf(sc[i][1] - mnew);
            float ps2 = __expf(sc[i][2] - mnew);
            float ps3 = __expf(sc[i][3] - mnew);
            float rsum = ps0 + ps1 + ps2 + ps3;
#pragma unroll
            for (int off = 8; off >= 1; off >>= 1)
                rsum += __shfl_xor_sync(0xffffffffu, rsum, off);

            li[i] = li[i] * alpha + rsum;
            mi[i] = mnew;
#pragma unroll
            for (int d = 0; d < 8; d++) acc[i][d] *= alpha;

            Ps[(r0 + i) * PPAD + tx]      = ps0;
            Ps[(r0 + i) * PPAD + tx + 16] = ps1;
            Ps[(r0 + i) * PPAD + tx + 32] = ps2;
            Ps[(r0 + i) * PPAD + tx + 48] = ps3;
        }
        __syncthreads();

        // ---- P @ V : each thread 2 rows x 8 d-cols (split 4+4) ----
#pragma unroll 4
        for (int n = 0; n < 64; n++) {
            float4 v0 = *(const float4*)&Vs[n * 128 + tx * 4];
            float4 v1 = *(const float4*)&Vs[n * 128 + 64 + tx * 4];
#pragma unroll
            for (int i = 0; i < 2; i++) {
                float p = Ps[(r0 + i) * PPAD + n];
                acc[i][0] = fmaf(p, v0.x, acc[i][0]);
                acc[i][1] = fmaf(p, v0.y, acc[i][1]);
                acc[i][2] = fmaf(p, v0.z, acc[i][2]);
                acc[i][3] = fmaf(p, v0.w, acc[i][3]);
                acc[i][4] = fmaf(p, v1.x, acc[i][4]);
                acc[i][5] = fmaf(p, v1.y, acc[i][5]);
                acc[i][6] = fmaf(p, v1.z, acc[i][6]);
                acc[i][7] = fmaf(p, v1.w, acc[i][7]);
            }
        }
        __syncthreads();
    }

    // ---- write O, packed as [b, s, h, d] ----
#pragma unroll
    for (int i = 0; i < 2; i++) {
        float inv = 1.0f / li[i];
        long row = rowbase + m0 + r0 + i;
        float4 o0 = make_float4(acc[i][0] * inv, acc[i][1] * inv,
                                acc[i][2] * inv, acc[i][3] * inv);
        float4 o1 = make_float4(acc[i][4] * inv, acc[i][5] * inv,
                                acc[i][6] * inv, acc[i][7] * inv);
        *(float4*)&outp[row * DMODEL + h * HD + tx * 4]      = o0;
        *(float4*)&outp[row * DMODEL + h * HD + 64 + tx * 4] = o1;
    }
}

// ======================= launch ============================================
extern "C" void kernel_launch(void* const* d_in, const int* in_sizes, int n_in,
                              void* d_out, int out_size)
{
    const float* x      = (const float*)d_in[0];
    const float* w_qkv  = (const float*)d_in[1];
    const float* b_qkv  = (const float*)d_in[2];
    const float* w_qup  = (const float*)d_in[3];
    const float* b_qup  = (const float*)d_in[4];
    const float* w_kup  = (const float*)d_in[5];
    const float* b_kup  = (const float*)d_in[6];
    const float* w_vup  = (const float*)d_in[7];
    const float* b_vup  = (const float*)d_in[8];
    const float* w_qpos = (const float*)d_in[9];
    const float* b_qpos = (const float*)d_in[10];
    const float* w_kpos = (const float*)d_in[11];
    const float* b_kpos = (const float*)d_in[12];
    const float* w_o    = (const float*)d_in[13];
    const float* b_o    = (const float*)d_in[14];
    float* out = (float*)d_out;

    float *latent, *qmain, *kmain, *vmain, *posq, *posk, *attnb;
    cudaGetSymbolAddress((void**)&latent, g_latent);
    cudaGetSymbolAddress((void**)&qmain,  g_qmain);
    cudaGetSymbolAddress((void**)&kmain,  g_kmain);
    cudaGetSymbolAddress((void**)&vmain,  g_vmain);
    cudaGetSymbolAddress((void**)&posq,   g_posq);
    cudaGetSymbolAddress((void**)&posk,   g_posk);
    cudaGetSymbolAddress((void**)&attnb,  g_attn);

    cudaFuncSetAttribute(attn_kernel,
                         cudaFuncAttributeMaxDynamicSharedMemorySize,
                         ATTN_SMEM_BYTES);

    dim3 blk(256);
    const int MG = MROWS / 128;  // 32 grid rows

    // latent_qkv = x @ w_qkv + b_qkv                [4096,1536]
    sgemm_bias<<<dim3(1536 / 128, MG), blk>>>(x, DMODEL, 0, w_qkv, 3 * LAT,
                                              b_qkv, latent, 3 * LAT,
                                              3 * LAT, DMODEL);
    // pos_k raw = x @ w_kpos + b_kpos               [4096,64]
    sgemm_bias<<<dim3(1, MG), blk>>>(x, DMODEL, 0, w_kpos, PHD,
                                     b_kpos, posk, PHD, PHD, DMODEL);
    // q_main = lq @ w_qup + b_qup                   [4096,2048]
    sgemm_bias<<<dim3(DMODEL / 128, MG), blk>>>(latent, 3 * LAT, 0, w_qup, DMODEL,
                                                b_qup, qmain, DMODEL, DMODEL, LAT);
    // k_main = lk @ w_kup + b_kup
    sgemm_bias<<<dim3(DMODEL / 128, MG), blk>>>(latent, 3 * LAT, LAT, w_kup, DMODEL,
                                                b_kup, kmain, DMODEL, DMODEL, LAT);
    // v_main = lv @ w_vup + b_vup
    sgemm_bias<<<dim3(DMODEL / 128, MG), blk>>>(latent, 3 * LAT, 2 * LAT, w_vup, DMODEL,
                                                b_vup, vmain, DMODEL, DMODEL, LAT);
    // pos_q raw = lq @ w_qpos + b_qpos              [4096,1024]
    sgemm_bias<<<dim3(1024 / 128, MG), blk>>>(latent, 3 * LAT, 0, w_qpos, NHD * PHD,
                                              b_qpos, posq, NHD * PHD, NHD * PHD, LAT);

    // RoPE (in place)
    rope_q_kernel<<<(MROWS * 512) / 256, 256>>>(posq);
    rope_k_kernel<<<(MROWS * 32) / 256, 256>>>(posk);

    // attention -> attnb packed [b, s, h, d]
    attn_kernel<<<dim3(SS / 64, BB * NHD), dim3(512), ATTN_SMEM_BYTES>>>(
        qmain, posq, kmain, posk, vmain, attnb);

    // out = attnb @ w_o + b_o                       [4096,2048]
    sgemm_bias<<<dim3(DMODEL / 128, MG), blk>>>(attnb, DMODEL, 0, w_o, DMODEL,
                                                b_o, out, DMODEL, DMODEL, DMODEL);
}

// round 7
// speedup vs baseline: 1.5046x; 1.1845x over previous
#include <cuda_runtime.h>
#include <math.h>
#include <stdint.h>

// Problem constants
#define BB     2
#define SS     2048
#define DMODEL 2048
#define LAT    512
#define NHD    16
#define HD     128
#define PHD    64
#define DQK    192     // HD + PHD
#define MROWS  4096    // BB * SS

// ---------------- scratch (static device globals; no allocation) ----------
__device__ float g_latent[MROWS * (3 * LAT)];   // [4096,1536]
__device__ float g_qmain [MROWS * DMODEL];      // [4096,2048]
__device__ float g_kmain [MROWS * DMODEL];
__device__ float g_vmain [MROWS * DMODEL];
__device__ float g_posq  [MROWS * (NHD * PHD)]; // [4096,1024]
__device__ float g_posk  [MROWS * PHD];         // [4096,64]
__device__ float g_attn  [MROWS * DMODEL];      // [b,s,h,d] packed

// ======================= generic SGEMM + bias ==============================
// C[m, n] = sum_k A[m*lda + aoff + k] * W[k*ldw + n] + bias[n]
// Tile 128x128x8, 256 threads, 8x8 per thread (rows {ty*4+i, 64+ty*4+i},
// cols {tx*4+j, 64+tx*4+j} -> conflict-free smem fragment reads).
// Double-buffered smem, register-staged global prefetch, 1 sync / k-tile.
__device__ __forceinline__
void sgemm_core(const float* __restrict__ A, int lda, int aoff,
                const float* __restrict__ W, int ldw,
                const float* __restrict__ bias,
                float* __restrict__ C, int ldc,
                int N, int K)
{
    __shared__ float As[2][8][128];   // transposed A tile
    __shared__ float Bs[2][8][128];

    const int tid  = threadIdx.x;
    const int m0   = blockIdx.y * 128;
    const int n0   = blockIdx.x * 128;

    const int arow = tid >> 1;          // 0..127
    const int acol = (tid & 1) * 4;     // 0 or 4
    const int brow = tid >> 5;          // 0..7
    const int bcol = (tid & 31) * 4;    // 0..124

    const int tx = tid & 15;
    const int ty = tid >> 4;

    float acc[8][8];
#pragma unroll
    for (int i = 0; i < 8; i++)
#pragma unroll
        for (int j = 0; j < 8; j++) acc[i][j] = 0.0f;

    const float* Aptr = A + (long)(m0 + arow) * lda + aoff + acol;
    const float* Wptr = W + (long)brow * ldw + n0 + bcol;
    const bool bvalid = (n0 + bcol) < N;

    // prologue: tile 0 -> buffer 0
    {
        float4 a = *(const float4*)(Aptr);
        float4 b = bvalid ? *(const float4*)(Wptr)
                          : make_float4(0.f, 0.f, 0.f, 0.f);
        As[0][acol + 0][arow] = a.x;
        As[0][acol + 1][arow] = a.y;
        As[0][acol + 2][arow] = a.z;
        As[0][acol + 3][arow] = a.w;
        *(float4*)&Bs[0][brow][bcol] = b;
    }
    __syncthreads();

    int nbuf = 1;
    for (int kt = 8; kt < K; kt += 8) {
        // prefetch next tile into registers
        float4 an = *(const float4*)(Aptr + kt);
        float4 bn = bvalid ? *(const float4*)(Wptr + (long)kt * ldw)
                           : make_float4(0.f, 0.f, 0.f, 0.f);

        const int cb = nbuf ^ 1;   // compute buffer
#pragma unroll
        for (int k = 0; k < 8; k++) {
            float4 a0 = *(const float4*)&As[cb][k][ty * 4];
            float4 a1 = *(const float4*)&As[cb][k][64 + ty * 4];
            float4 b0 = *(const float4*)&Bs[cb][k][tx * 4];
            float4 b1 = *(const float4*)&Bs[cb][k][64 + tx * 4];
            float ar[8] = {a0.x, a0.y, a0.z, a0.w, a1.x, a1.y, a1.z, a1.w};
            float br[8] = {b0.x, b0.y, b0.z, b0.w, b1.x, b1.y, b1.z, b1.w};
#pragma unroll
            for (int i = 0; i < 8; i++)
#pragma unroll
                for (int j = 0; j < 8; j++)
                    acc[i][j] = fmaf(ar[i], br[j], acc[i][j]);
        }

        // store prefetched tile into the other buffer
        As[nbuf][acol + 0][arow] = an.x;
        As[nbuf][acol + 1][arow] = an.y;
        As[nbuf][acol + 2][arow] = an.z;
        As[nbuf][acol + 3][arow] = an.w;
        *(float4*)&Bs[nbuf][brow][bcol] = bn;
        __syncthreads();
        nbuf ^= 1;
    }

    // final tile
    {
        const int cb = nbuf ^ 1;
#pragma unroll
        for (int k = 0; k < 8; k++) {
            float4 a0 = *(const float4*)&As[cb][k][ty * 4];
            float4 a1 = *(const float4*)&As[cb][k][64 + ty * 4];
            float4 b0 = *(const float4*)&Bs[cb][k][tx * 4];
            float4 b1 = *(const float4*)&Bs[cb][k][64 + tx * 4];
            float ar[8] = {a0.x, a0.y, a0.z, a0.w, a1.x, a1.y, a1.z, a1.w};
            float br[8] = {b0.x, b0.y, b0.z, b0.w, b1.x, b1.y, b1.z, b1.w};
#pragma unroll
            for (int i = 0; i < 8; i++)
#pragma unroll
                for (int j = 0; j < 8; j++)
                    acc[i][j] = fmaf(ar[i], br[j], acc[i][j]);
        }
    }

    // epilogue (col groups are fully valid or fully invalid: N % 64 == 0)
    const int nc0 = n0 + tx * 4;
    const int nc1 = n0 + 64 + tx * 4;
    const bool v0 = nc0 < N;
    const bool v1 = nc1 < N;
    float4 bb0 = v0 ? *(const float4*)&bias[nc0] : make_float4(0,0,0,0);
    float4 bb1 = v1 ? *(const float4*)&bias[nc1] : make_float4(0,0,0,0);

#pragma unroll
    for (int g = 0; g < 2; g++) {
#pragma unroll
        for (int i = 0; i < 4; i++) {
            long m = m0 + g * 64 + ty * 4 + i;
            const float* ac = acc[g * 4 + i];
            if (v0) {
                float4 o = make_float4(ac[0] + bb0.x, ac[1] + bb0.y,
                                       ac[2] + bb0.z, ac[3] + bb0.w);
                *(float4*)&C[m * ldc + nc0] = o;
            }
            if (v1) {
                float4 o = make_float4(ac[4] + bb1.x, ac[5] + bb1.y,
                                       ac[6] + bb1.z, ac[7] + bb1.w);
                *(float4*)&C[m * ldc + nc1] = o;
            }
        }
    }
}

__global__ __launch_bounds__(256, 2)
void sgemm_bias(const float* __restrict__ A, int lda, int aoff,
                const float* __restrict__ W, int ldw,
                const float* __restrict__ bias,
                float* __restrict__ C, int ldc,
                int N, int K)
{
    sgemm_core(A, lda, aoff, W, ldw, bias, C, ldc, N, K);
}

// three up-projections in one launch (blockIdx.z selects q/k/v)
__global__ __launch_bounds__(256, 2)
void sgemm_up3(const float* __restrict__ latent,
               const float* __restrict__ w0, const float* __restrict__ b0, float* __restrict__ c0,
               const float* __restrict__ w1, const float* __restrict__ b1, float* __restrict__ c1,
               const float* __restrict__ w2, const float* __restrict__ b2, float* __restrict__ c2)
{
    const int z = blockIdx.z;
    const float* W  = (z == 0) ? w0 : (z == 1) ? w1 : w2;
    const float* Bb = (z == 0) ? b0 : (z == 1) ? b1 : b2;
    float*       C  = (z == 0) ? c0 : (z == 1) ? c1 : c2;
    sgemm_core(latent, 3 * LAT, z * LAT, W, DMODEL, Bb, C, DMODEL, DMODEL, LAT);
}

// ======================= fused RoPE kernel =================================
// inv_freq[i] = 50000^(-i/32) = 2^(-i * log2(50000)/32)
#define LOG2_THETA_OVER_32 0.48780126482613787f
#define QROT (MROWS * 512)   // pos_q rotation pairs
#define KROT (MROWS * 32)    // pos_k rotation pairs

__global__ void rope_kernel(float* __restrict__ pq, float* __restrict__ pk)
{
    int idx = blockIdx.x * 256 + threadIdx.x;
    if (idx >= QROT + KROT) return;

    float* base;
    int s, i;
    if (idx < QROT) {
        int r   = idx >> 9;
        int rem = idx & 511;
        int h   = rem >> 5;
        i       = rem & 31;
        s       = r & (SS - 1);
        base = pq + (long)r * (NHD * PHD) + h * PHD + i;
    } else {
        int k = idx - QROT;
        int r = k >> 5;
        i     = k & 31;
        s     = r & (SS - 1);
        base = pk + (long)r * PHD + i;
    }

    float invf = exp2f(-(float)i * LOG2_THETA_OVER_32);
    float ang  = (float)s * invf;
    float sn, cs;
    sincosf(ang, &sn, &cs);

    float x0 = base[0], x1 = base[32];
    base[0]  = x0 * cs - x1 * sn;
    base[32] = x1 * cs + x0 * sn;
}

// ======================= flash attention ===================================
// grid = (32 q-tiles, 32 batch*head). block = 512 (ty 0..31 -> 2 rows each,
// tx 0..15). Score cols {tx,tx+16,tx+32,tx+48}; output cols split
// {4tx..4tx+3} and {64+4tx..64+4tx+3} (conflict-free V reads).
// K/V tiles double-buffered via cp.async (prefetch t+1 while computing t).
#define QPAD 192
#define KPAD 196
#define PPAD 64
#define KTILE_FLOATS (64 * KPAD)
#define VTILE_FLOATS (64 * 128)
#define ATTN_SMEM_FLOATS (64 * QPAD + 2 * KTILE_FLOATS + 2 * VTILE_FLOATS + 64 * PPAD)
#define ATTN_SMEM_BYTES  (ATTN_SMEM_FLOATS * 4)   // 231,424 B

__device__ __forceinline__ void cp_async16(void* smem_dst, const void* gmem_src)
{
    uint32_t dst = (uint32_t)__cvta_generic_to_shared(smem_dst);
    asm volatile("cp.async.cg.shared.global [%0], [%1], 16;\n"
                 :: "r"(dst), "l"(gmem_src));
}

__device__ __forceinline__ void load_kv_async(
    const float* __restrict__ kmain, const float* __restrict__ posk,
    const float* __restrict__ vmain,
    long rowbase, int h, int n0, float* Ksb, float* Vsb, int tid)
{
    // K tile: 64 rows x 48 float4-chunks (32 main + 16 pos) = 3072 chunks
#pragma unroll
    for (int j = 0; j < 6; j++) {
        int c   = tid + j * 512;
        int row = c / 48;
        int dc  = c % 48;
        const float* src = (dc < 32)
            ? kmain + (rowbase + n0 + row) * DMODEL + h * HD + dc * 4
            : posk  + (rowbase + n0 + row) * PHD + (dc - 32) * 4;
        cp_async16(Ksb + row * KPAD + dc * 4, src);
    }
    // V tile: 64 rows x 32 float4-chunks = 2048 chunks
#pragma unroll
    for (int j = 0; j < 4; j++) {
        int c   = tid + j * 512;
        int row = c >> 5;
        int dc  = c & 31;
        cp_async16(Vsb + row * 128 + dc * 4,
                   vmain + (rowbase + n0 + row) * DMODEL + h * HD + dc * 4);
    }
}

__global__ __launch_bounds__(512, 1)
void attn_kernel(const float* __restrict__ qmain, const float* __restrict__ posq,
                 const float* __restrict__ kmain, const float* __restrict__ posk,
                 const float* __restrict__ vmain, float* __restrict__ outp)
{
    extern __shared__ float sm[];
    float* Qs = sm;                          // [64][QPAD]
    float* Ks = Qs + 64 * QPAD;              // 2 x [64][KPAD]
    float* Vs = Ks + 2 * KTILE_FLOATS;       // 2 x [64][128]
    float* Ps = Vs + 2 * VTILE_FLOATS;       // [64][PPAD]

    const int bh = blockIdx.y;
    const int b  = bh >> 4;
    const int h  = bh & 15;
    const int qt = (int)gridDim.x - 1 - (int)blockIdx.x;  // heavy tiles first
    const int m0 = qt * 64;

    const int tid = threadIdx.x;
    const int tx  = tid & 15;
    const int ty  = tid >> 4;
    const int r0  = ty * 2;

    const long rowbase = (long)b * SS;
    const float scale = 0.07216878364870323f;  // 1/sqrt(192)

    // ---- prefetch K/V tile 0 into buffer 0 ----
    load_kv_async(kmain, posk, vmain, rowbase, h, 0, Ks, Vs, tid);
    asm volatile("cp.async.commit_group;\n" ::: "memory");

    // ---- load Q tile (once per block, plain loads) ----
    for (int idx = tid; idx < 64 * DQK; idx += 512) {
        int m = idx / DQK, d = idx % DQK;
        float v;
        if (d < HD) v = qmain[(rowbase + m0 + m) * DMODEL + h * HD + d];
        else        v = posq [(rowbase + m0 + m) * (NHD * PHD) + h * PHD + (d - HD)];
        Qs[m * QPAD + d] = v;
    }

    float mi[2], li[2], acc[2][8];
#pragma unroll
    for (int i = 0; i < 2; i++) {
        mi[i] = -1e30f;
        li[i] = 0.0f;
#pragma unroll
        for (int j = 0; j < 8; j++) acc[i][j] = 0.0f;
    }

    for (int t = 0; t <= qt; ++t) {
        const int buf = t & 1;
        float* Ksb = Ks + buf * KTILE_FLOATS;
        float* Vsb = Vs + buf * VTILE_FLOATS;

        // prefetch tile t+1 into the other buffer (its readers finished at
        // the end of iteration t-1)
        if (t < qt) {
            load_kv_async(kmain, posk, vmain, rowbase, h, (t + 1) * 64,
                          Ks + (buf ^ 1) * KTILE_FLOATS,
                          Vs + (buf ^ 1) * VTILE_FLOATS, tid);
        }
        asm volatile("cp.async.commit_group;\n" ::: "memory");
        asm volatile("cp.async.wait_group 1;\n" ::: "memory");
        __syncthreads();

        const int n0 = t * 64;

        // ---- scores: 2 rows x 4 cols per thread over DQK=192 ----
        float sc[2][4];
#pragma unroll
        for (int i = 0; i < 2; i++)
#pragma unroll
            for (int j = 0; j < 4; j++) sc[i][j] = 0.0f;

#pragma unroll 4
        for (int k4 = 0; k4 < DQK; k4 += 4) {
            float4 qv[2], kv[4];
#pragma unroll
            for (int i = 0; i < 2; i++)
                qv[i] = *(const float4*)&Qs[(r0 + i) * QPAD + k4];
#pragma unroll
            for (int j = 0; j < 4; j++)
                kv[j] = *(const float4*)&Ksb[(tx + 16 * j) * KPAD + k4];
#pragma unroll
            for (int i = 0; i < 2; i++)
#pragma unroll
                for (int j = 0; j < 4; j++) {
                    sc[i][j] = fmaf(qv[i].x, kv[j].x, sc[i][j]);
                    sc[i][j] = fmaf(qv[i].y, kv[j].y, sc[i][j]);
                    sc[i][j] = fmaf(qv[i].z, kv[j].z, sc[i][j]);
                    sc[i][j] = fmaf(qv[i].w, kv[j].w, sc[i][j]);
                }
        }

        // scale + causal mask (mask only possible on the diagonal tile)
        const bool diag = (t == qt);
#pragma unroll
        for (int i = 0; i < 2; i++)
#pragma unroll
            for (int j = 0; j < 4; j++) {
                sc[i][j] *= scale;
                if (diag) {
                    int nq = n0 + tx + 16 * j;
                    int mq = m0 + r0 + i;
                    if (nq > mq) sc[i][j] = -1e30f;
                }
            }

        // ---- online softmax update (per row, reduced across 16 tx lanes) --
#pragma unroll
        for (int i = 0; i < 2; i++) {
            float tmax = fmaxf(fmaxf(sc[i][0], sc[i][1]), fmaxf(sc[i][2], sc[i][3]));
#pragma unroll
            for (int off = 8; off >= 1; off >>= 1)
                tmax = fmaxf(tmax, __shfl_xor_sync(0xffffffffu, tmax, off));

            float mnew  = fmaxf(mi[i], tmax);
            float alpha = __expf(mi[i] - mnew);

            float ps0 = __expf(sc[i][0] - mnew);
            float ps1 = __expf(sc[i][1] - mnew);
            float ps2 = __expf(sc[i][2] - mnew);
            float ps3 = __expf(sc[i][3] - mnew);
            float rsum = ps0 + ps1 + ps2 + ps3;
#pragma unroll
            for (int off = 8; off >= 1; off >>= 1)
                rsum += __shfl_xor_sync(0xffffffffu, rsum, off);

            li[i] = li[i] * alpha + rsum;
            mi[i] = mnew;
#pragma unroll
            for (int d = 0; d < 8; d++) acc[i][d] *= alpha;

            Ps[(r0 + i) * PPAD + tx]      = ps0;
            Ps[(r0 + i) * PPAD + tx + 16] = ps1;
            Ps[(r0 + i) * PPAD + tx + 32] = ps2;
            Ps[(r0 + i) * PPAD + tx + 48] = ps3;
        }
        __syncthreads();

        // ---- P @ V : each thread 2 rows x 8 d-cols (split 4+4) ----
#pragma unroll 4
        for (int n = 0; n < 64; n++) {
            float4 v0 = *(const float4*)&Vsb[n * 128 + tx * 4];
            float4 v1 = *(const float4*)&Vsb[n * 128 + 64 + tx * 4];
#pragma unroll
            for (int i = 0; i < 2; i++) {
                float p = Ps[(r0 + i) * PPAD + n];
                acc[i][0] = fmaf(p, v0.x, acc[i][0]);
                acc[i][1] = fmaf(p, v0.y, acc[i][1]);
                acc[i][2] = fmaf(p, v0.z, acc[i][2]);
                acc[i][3] = fmaf(p, v0.w, acc[i][3]);
                acc[i][4] = fmaf(p, v1.x, acc[i][4]);
                acc[i][5] = fmaf(p, v1.y, acc[i][5]);
                acc[i][6] = fmaf(p, v1.z, acc[i][6]);
                acc[i][7] = fmaf(p, v1.w, acc[i][7]);
            }
        }
        __syncthreads();
    }

    // ---- write O, packed as [b, s, h, d] ----
#pragma unroll
    for (int i = 0; i < 2; i++) {
        float inv = 1.0f / li[i];
        long row = rowbase + m0 + r0 + i;
        float4 o0 = make_float4(acc[i][0] * inv, acc[i][1] * inv,
                                acc[i][2] * inv, acc[i][3] * inv);
        float4 o1 = make_float4(acc[i][4] * inv, acc[i][5] * inv,
                                acc[i][6] * inv, acc[i][7] * inv);
        *(float4*)&outp[row * DMODEL + h * HD + tx * 4]      = o0;
        *(float4*)&outp[row * DMODEL + h * HD + 64 + tx * 4] = o1;
    }
}

// ======================= launch ============================================
extern "C" void kernel_launch(void* const* d_in, const int* in_sizes, int n_in,
                              void* d_out, int out_size)
{
    const float* x      = (const float*)d_in[0];
    const float* w_qkv  = (const float*)d_in[1];
    const float* b_qkv  = (const float*)d_in[2];
    const float* w_qup  = (const float*)d_in[3];
    const float* b_qup  = (const float*)d_in[4];
    const float* w_kup  = (const float*)d_in[5];
    const float* b_kup  = (const float*)d_in[6];
    const float* w_vup  = (const float*)d_in[7];
    const float* b_vup  = (const float*)d_in[8];
    const float* w_qpos = (const float*)d_in[9];
    const float* b_qpos = (const float*)d_in[10];
    const float* w_kpos = (const float*)d_in[11];
    const float* b_kpos = (const float*)d_in[12];
    const float* w_o    = (const float*)d_in[13];
    const float* b_o    = (const float*)d_in[14];
    float* out = (float*)d_out;

    float *latent, *qmain, *kmain, *vmain, *posq, *posk, *attnb;
    cudaGetSymbolAddress((void**)&latent, g_latent);
    cudaGetSymbolAddress((void**)&qmain,  g_qmain);
    cudaGetSymbolAddress((void**)&kmain,  g_kmain);
    cudaGetSymbolAddress((void**)&vmain,  g_vmain);
    cudaGetSymbolAddress((void**)&posq,   g_posq);
    cudaGetSymbolAddress((void**)&posk,   g_posk);
    cudaGetSymbolAddress((void**)&attnb,  g_attn);

    cudaFuncSetAttribute(attn_kernel,
                         cudaFuncAttributeMaxDynamicSharedMemorySize,
                         ATTN_SMEM_BYTES);

    dim3 blk(256);
    const int MG = MROWS / 128;  // 32 grid rows

    // 1) latent_qkv = x @ w_qkv + b_qkv             [4096,1536]
    sgemm_bias<<<dim3(1536 / 128, MG), blk>>>(x, DMODEL, 0, w_qkv, 3 * LAT,
                                              b_qkv, latent, 3 * LAT,
                                              3 * LAT, DMODEL);
    // 2) pos_k raw = x @ w_kpos + b_kpos            [4096,64]
    sgemm_bias<<<dim3(1, MG), blk>>>(x, DMODEL, 0, w_kpos, PHD,
                                     b_kpos, posk, PHD, PHD, DMODEL);
    // 3) q/k/v up-projections in one launch         3 x [4096,2048]
    sgemm_up3<<<dim3(DMODEL / 128, MG, 3), blk>>>(latent,
                                                  w_qup, b_qup, qmain,
                                                  w_kup, b_kup, kmain,
                                                  w_vup, b_vup, vmain);
    // 4) pos_q raw = lq @ w_qpos + b_qpos           [4096,1024]
    sgemm_bias<<<dim3(1024 / 128, MG), blk>>>(latent, 3 * LAT, 0, w_qpos, NHD * PHD,
                                              b_qpos, posq, NHD * PHD, NHD * PHD, LAT);
    // 5) RoPE (in place, fused q+k)
    rope_kernel<<<(QROT + KROT + 255) / 256, 256>>>(posq, posk);

    // 6) attention -> attnb packed [b, s, h, d]
    attn_kernel<<<dim3(SS / 64, BB * NHD), dim3(512), ATTN_SMEM_BYTES>>>(
        qmain, posq, kmain, posk, vmain, attnb);

    // 7) out = attnb @ w_o + b_o                    [4096,2048]
    sgemm_bias<<<dim3(DMODEL / 128, MG), blk>>>(attnb, DMODEL, 0, w_o, DMODEL,
                                                b_o, out, DMODEL, DMODEL, DMODEL);
}

// round 8
// speedup vs baseline: 1.6009x; 1.0640x over previous
#include <cuda_runtime.h>
#include <math.h>
#include <stdint.h>

// Problem constants
#define BB     2
#define SS     2048
#define DMODEL 2048
#define LAT    512
#define NHD    16
#define HD     128
#define PHD    64
#define DQK    192     // HD + PHD
#define MROWS  4096    // BB * SS

// ---------------- scratch (static device globals; no allocation) ----------
__device__ float g_latent[MROWS * (3 * LAT)];   // [4096,1536]
__device__ float g_qmain [MROWS * DMODEL];      // [4096,2048]
__device__ float g_kmain [MROWS * DMODEL];
__device__ float g_vmain [MROWS * DMODEL];
__device__ float g_posq  [MROWS * (NHD * PHD)]; // [4096,1024]
__device__ float g_posk  [MROWS * PHD];         // [4096,64]
__device__ float g_attn  [MROWS * DMODEL];      // [b,s,h,d] packed

// ======================= generic SGEMM + bias ==============================
__device__ __forceinline__
void sgemm_core(const float* __restrict__ A, int lda, int aoff,
                const float* __restrict__ W, int ldw,
                const float* __restrict__ bias,
                float* __restrict__ C, int ldc,
                int N, int K)
{
    __shared__ float As[2][8][128];   // transposed A tile
    __shared__ float Bs[2][8][128];

    const int tid  = threadIdx.x;
    const int m0   = blockIdx.y * 128;
    const int n0   = blockIdx.x * 128;

    const int arow = tid >> 1;          // 0..127
    const int acol = (tid & 1) * 4;     // 0 or 4
    const int brow = tid >> 5;          // 0..7
    const int bcol = (tid & 31) * 4;    // 0..124

    const int tx = tid & 15;
    const int ty = tid >> 4;

    float acc[8][8];
#pragma unroll
    for (int i = 0; i < 8; i++)
#pragma unroll
        for (int j = 0; j < 8; j++) acc[i][j] = 0.0f;

    const float* Aptr = A + (long)(m0 + arow) * lda + aoff + acol;
    const float* Wptr = W + (long)brow * ldw + n0 + bcol;
    const bool bvalid = (n0 + bcol) < N;

    // prologue: tile 0 -> buffer 0
    {
        float4 a = *(const float4*)(Aptr);
        float4 b = bvalid ? *(const float4*)(Wptr)
                          : make_float4(0.f, 0.f, 0.f, 0.f);
        As[0][acol + 0][arow] = a.x;
        As[0][acol + 1][arow] = a.y;
        As[0][acol + 2][arow] = a.z;
        As[0][acol + 3][arow] = a.w;
        *(float4*)&Bs[0][brow][bcol] = b;
    }
    __syncthreads();

    int nbuf = 1;
    for (int kt = 8; kt < K; kt += 8) {
        float4 an = *(const float4*)(Aptr + kt);
        float4 bn = bvalid ? *(const float4*)(Wptr + (long)kt * ldw)
                           : make_float4(0.f, 0.f, 0.f, 0.f);

        const int cb = nbuf ^ 1;   // compute buffer
#pragma unroll
        for (int k = 0; k < 8; k++) {
            float4 a0 = *(const float4*)&As[cb][k][ty * 4];
            float4 a1 = *(const float4*)&As[cb][k][64 + ty * 4];
            float4 b0 = *(const float4*)&Bs[cb][k][tx * 4];
            float4 b1 = *(const float4*)&Bs[cb][k][64 + tx * 4];
            float ar[8] = {a0.x, a0.y, a0.z, a0.w, a1.x, a1.y, a1.z, a1.w};
            float br[8] = {b0.x, b0.y, b0.z, b0.w, b1.x, b1.y, b1.z, b1.w};
#pragma unroll
            for (int i = 0; i < 8; i++)
#pragma unroll
                for (int j = 0; j < 8; j++)
                    acc[i][j] = fmaf(ar[i], br[j], acc[i][j]);
        }

        As[nbuf][acol + 0][arow] = an.x;
        As[nbuf][acol + 1][arow] = an.y;
        As[nbuf][acol + 2][arow] = an.z;
        As[nbuf][acol + 3][arow] = an.w;
        *(float4*)&Bs[nbuf][brow][bcol] = bn;
        __syncthreads();
        nbuf ^= 1;
    }

    {
        const int cb = nbuf ^ 1;
#pragma unroll
        for (int k = 0; k < 8; k++) {
            float4 a0 = *(const float4*)&As[cb][k][ty * 4];
            float4 a1 = *(const float4*)&As[cb][k][64 + ty * 4];
            float4 b0 = *(const float4*)&Bs[cb][k][tx * 4];
            float4 b1 = *(const float4*)&Bs[cb][k][64 + tx * 4];
            float ar[8] = {a0.x, a0.y, a0.z, a0.w, a1.x, a1.y, a1.z, a1.w};
            float br[8] = {b0.x, b0.y, b0.z, b0.w, b1.x, b1.y, b1.z, b1.w};
#pragma unroll
            for (int i = 0; i < 8; i++)
#pragma unroll
                for (int j = 0; j < 8; j++)
                    acc[i][j] = fmaf(ar[i], br[j], acc[i][j]);
        }
    }

    const int nc0 = n0 + tx * 4;
    const int nc1 = n0 + 64 + tx * 4;
    const bool v0 = nc0 < N;
    const bool v1 = nc1 < N;
    float4 bb0 = v0 ? *(const float4*)&bias[nc0] : make_float4(0,0,0,0);
    float4 bb1 = v1 ? *(const float4*)&bias[nc1] : make_float4(0,0,0,0);

#pragma unroll
    for (int g = 0; g < 2; g++) {
#pragma unroll
        for (int i = 0; i < 4; i++) {
            long m = m0 + g * 64 + ty * 4 + i;
            const float* ac = acc[g * 4 + i];
            if (v0) {
                float4 o = make_float4(ac[0] + bb0.x, ac[1] + bb0.y,
                                       ac[2] + bb0.z, ac[3] + bb0.w);
                *(float4*)&C[m * ldc + nc0] = o;
            }
            if (v1) {
                float4 o = make_float4(ac[4] + bb1.x, ac[5] + bb1.y,
                                       ac[6] + bb1.z, ac[7] + bb1.w);
                *(float4*)&C[m * ldc + nc1] = o;
            }
        }
    }
}

__global__ __launch_bounds__(256, 2)
void sgemm_bias(const float* __restrict__ A, int lda, int aoff,
                const float* __restrict__ W, int ldw,
                const float* __restrict__ bias,
                float* __restrict__ C, int ldc,
                int N, int K)
{
    sgemm_core(A, lda, aoff, W, ldw, bias, C, ldc, N, K);
}

// three up-projections in one launch (blockIdx.z selects q/k/v)
__global__ __launch_bounds__(256, 2)
void sgemm_up3(const float* __restrict__ latent,
               const float* __restrict__ w0, const float* __restrict__ b0, float* __restrict__ c0,
               const float* __restrict__ w1, const float* __restrict__ b1, float* __restrict__ c1,
               const float* __restrict__ w2, const float* __restrict__ b2, float* __restrict__ c2)
{
    const int z = blockIdx.z;
    const float* W  = (z == 0) ? w0 : (z == 1) ? w1 : w2;
    const float* Bb = (z == 0) ? b0 : (z == 1) ? b1 : b2;
    float*       C  = (z == 0) ? c0 : (z == 1) ? c1 : c2;
    sgemm_core(latent, 3 * LAT, z * LAT, W, DMODEL, Bb, C, DMODEL, DMODEL, LAT);
}

// ======================= fused RoPE kernel =================================
#define LOG2_THETA_OVER_32 0.48780126482613787f
#define QROT (MROWS * 512)   // pos_q rotation pairs
#define KROT (MROWS * 32)    // pos_k rotation pairs

__global__ void rope_kernel(float* __restrict__ pq, float* __restrict__ pk)
{
    int idx = blockIdx.x * 256 + threadIdx.x;
    if (idx >= QROT + KROT) return;

    float* base;
    int s, i;
    if (idx < QROT) {
        int r   = idx >> 9;
        int rem = idx & 511;
        int h   = rem >> 5;
        i       = rem & 31;
        s       = r & (SS - 1);
        base = pq + (long)r * (NHD * PHD) + h * PHD + i;
    } else {
        int k = idx - QROT;
        int r = k >> 5;
        i     = k & 31;
        s     = r & (SS - 1);
        base = pk + (long)r * PHD + i;
    }

    float invf = exp2f(-(float)i * LOG2_THETA_OVER_32);
    float ang  = (float)s * invf;
    float sn, cs;
    sincosf(ang, &sn, &cs);

    float x0 = base[0], x1 = base[32];
    base[0]  = x0 * cs - x1 * sn;
    base[32] = x1 * cs + x0 * sn;
}

// ======================= flash attention v3 ================================
// 128x64 tiles. 512 threads: tx 0..15, ty 0..31; each thread 4 q-rows
// (r0=4ty), score cols {tx+16j}; output cols {4tx, 64+4tx}.
// Single-buffered K/V with cp.async pipelined across stages:
//   K(t+1) issued after softmax barrier (covered by P@V),
//   V(t+1) issued after P@V barrier (covered by next score stage).
#define QTILE 128
#define KTILE 64
#define QPAD 196
#define KPAD 196
#define PPAD 68
#define ATTN_SMEM_FLOATS (QTILE * QPAD + KTILE * KPAD + KTILE * 128 + QTILE * PPAD)
#define ATTN_SMEM_BYTES  (ATTN_SMEM_FLOATS * 4)   // 218,112 B

__device__ __forceinline__ void cp_async16(void* smem_dst, const void* gmem_src)
{
    uint32_t dst = (uint32_t)__cvta_generic_to_shared(smem_dst);
    asm volatile("cp.async.cg.shared.global [%0], [%1], 16;\n"
                 :: "r"(dst), "l"(gmem_src));
}

__device__ __forceinline__ void load_k_async(
    const float* __restrict__ kmain, const float* __restrict__ posk,
    long rowbase, int h, int n0, float* Ks, int tid)
{
    // 64 rows x 48 float4-chunks (32 main + 16 pos) = 3072 chunks
#pragma unroll
    for (int j = 0; j < 6; j++) {
        int c   = tid + j * 512;
        int row = c / 48;
        int dc  = c % 48;
        const float* src = (dc < 32)
            ? kmain + (rowbase + n0 + row) * DMODEL + h * HD + dc * 4
            : posk  + (rowbase + n0 + row) * PHD + (dc - 32) * 4;
        cp_async16(Ks + row * KPAD + dc * 4, src);
    }
}

__device__ __forceinline__ void load_v_async(
    const float* __restrict__ vmain,
    long rowbase, int h, int n0, float* Vs, int tid)
{
    // 64 rows x 32 float4-chunks = 2048 chunks
#pragma unroll
    for (int j = 0; j < 4; j++) {
        int c   = tid + j * 512;
        int row = c >> 5;
        int dc  = c & 31;
        cp_async16(Vs + row * 128 + dc * 4,
                   vmain + (rowbase + n0 + row) * DMODEL + h * HD + dc * 4);
    }
}

__global__ __launch_bounds__(512, 1)
void attn_kernel(const float* __restrict__ qmain, const float* __restrict__ posq,
                 const float* __restrict__ kmain, const float* __restrict__ posk,
                 const float* __restrict__ vmain, float* __restrict__ outp)
{
    extern __shared__ float sm[];
    float* Qs = sm;                          // [128][QPAD]
    float* Ks = Qs + QTILE * QPAD;           // [64][KPAD]
    float* Vs = Ks + KTILE * KPAD;           // [64][128]
    float* Ps = Vs + KTILE * 128;            // [128][PPAD]

    const int bh  = blockIdx.y;
    const int b   = bh >> 4;
    const int h   = bh & 15;
    const int qti = (int)gridDim.x - 1 - (int)blockIdx.x;  // heavy tiles first
    const int m0  = qti * QTILE;
    const int nk  = 2 * qti + 2;             // k-tiles covering rows < m0+128

    const int tid = threadIdx.x;
    const int tx  = tid & 15;
    const int ty  = tid >> 4;
    const int r0  = ty * 4;

    const long rowbase = (long)b * SS;
    const float scale = 0.07216878364870323f;  // 1/sqrt(192)

    // ---- prefetch K/V tile 0 and Q tile (all cp.async, one group) ----
    load_k_async(kmain, posk, rowbase, h, 0, Ks, tid);
    load_v_async(vmain, rowbase, h, 0, Vs, tid);
    // Q: 128 rows x 48 float4-chunks = 6144 chunks
#pragma unroll
    for (int j = 0; j < 12; j++) {
        int c   = tid + j * 512;
        int row = c / 48;
        int dc  = c % 48;
        const float* src = (dc < 32)
            ? qmain + (rowbase + m0 + row) * DMODEL + h * HD + dc * 4
            : posq  + (rowbase + m0 + row) * (NHD * PHD) + h * PHD + (dc - 32) * 4;
        cp_async16(Qs + row * QPAD + dc * 4, src);
    }
    asm volatile("cp.async.commit_group;\n" ::: "memory");

    float mi[4], li[4], acc[4][8];
#pragma unroll
    for (int i = 0; i < 4; i++) {
        mi[i] = -1e30f;
        li[i] = 0.0f;
#pragma unroll
        for (int j = 0; j < 8; j++) acc[i][j] = 0.0f;
    }

    for (int t = 0; t < nk; ++t) {
        asm volatile("cp.async.wait_group 0;\n" ::: "memory");
        __syncthreads();   // barrier A: K(t), V(t) (and Q) visible

        const int n0 = t * KTILE;

        // ---- scores: 4 rows x 4 cols per thread over DQK=192 ----
        float sc[4][4];
#pragma unroll
        for (int i = 0; i < 4; i++)
#pragma unroll
            for (int j = 0; j < 4; j++) sc[i][j] = 0.0f;

#pragma unroll 2
        for (int k4 = 0; k4 < DQK; k4 += 4) {
            float4 qv[4], kv[4];
#pragma unroll
            for (int i = 0; i < 4; i++)
                qv[i] = *(const float4*)&Qs[(r0 + i) * QPAD + k4];
#pragma unroll
            for (int j = 0; j < 4; j++)
                kv[j] = *(const float4*)&Ks[(tx + 16 * j) * KPAD + k4];
#pragma unroll
            for (int i = 0; i < 4; i++)
#pragma unroll
                for (int j = 0; j < 4; j++) {
                    sc[i][j] = fmaf(qv[i].x, kv[j].x, sc[i][j]);
                    sc[i][j] = fmaf(qv[i].y, kv[j].y, sc[i][j]);
                    sc[i][j] = fmaf(qv[i].z, kv[j].z, sc[i][j]);
                    sc[i][j] = fmaf(qv[i].w, kv[j].w, sc[i][j]);
                }
        }

        // scale + causal mask (only the last two k-tiles touch the diagonal)
        const bool diag = (t >= 2 * qti);
#pragma unroll
        for (int i = 0; i < 4; i++)
#pragma unroll
            for (int j = 0; j < 4; j++) {
                sc[i][j] *= scale;
                if (diag) {
                    int nq = n0 + tx + 16 * j;
                    int mq = m0 + r0 + i;
                    if (nq > mq) sc[i][j] = -1e30f;
                }
            }

        // ---- online softmax update (per row, reduced across 16 tx lanes) --
#pragma unroll
        for (int i = 0; i < 4; i++) {
            float tmax = fmaxf(fmaxf(sc[i][0], sc[i][1]), fmaxf(sc[i][2], sc[i][3]));
#pragma unroll
            for (int off = 8; off >= 1; off >>= 1)
                tmax = fmaxf(tmax, __shfl_xor_sync(0xffffffffu, tmax, off));

            float mnew  = fmaxf(mi[i], tmax);
            float alpha = __expf(mi[i] - mnew);

            float ps0 = __expf(sc[i][0] - mnew);
            float ps1 = __expf(sc[i][1] - mnew);
            float ps2 = __expf(sc[i][2] - mnew);
            float ps3 = __expf(sc[i][3] - mnew);
            float rsum = ps0 + ps1 + ps2 + ps3;
#pragma unroll
            for (int off = 8; off >= 1; off >>= 1)
                rsum += __shfl_xor_sync(0xffffffffu, rsum, off);

            li[i] = li[i] * alpha + rsum;
            mi[i] = mnew;
#pragma unroll
            for (int d = 0; d < 8; d++) acc[i][d] *= alpha;

            Ps[(r0 + i) * PPAD + tx]      = ps0;
            Ps[(r0 + i) * PPAD + tx + 16] = ps1;
            Ps[(r0 + i) * PPAD + tx + 32] = ps2;
            Ps[(r0 + i) * PPAD + tx + 48] = ps3;
        }
        __syncthreads();   // barrier B: Ps ready; all K reads done

        // prefetch K(t+1) — overlaps with P@V below
        if (t + 1 < nk) {
            load_k_async(kmain, posk, rowbase, h, (t + 1) * KTILE, Ks, tid);
            asm volatile("cp.async.commit_group;\n" ::: "memory");
        }

        // ---- P @ V : each thread 4 rows x 8 d-cols (split 4+4) ----
#pragma unroll 2
        for (int n = 0; n < KTILE; n++) {
            float4 v0 = *(const float4*)&Vs[n * 128 + tx * 4];
            float4 v1 = *(const float4*)&Vs[n * 128 + 64 + tx * 4];
#pragma unroll
            for (int i = 0; i < 4; i++) {
                float p = Ps[(r0 + i) * PPAD + n];
                acc[i][0] = fmaf(p, v0.x, acc[i][0]);
                acc[i][1] = fmaf(p, v0.y, acc[i][1]);
                acc[i][2] = fmaf(p, v0.z, acc[i][2]);
                acc[i][3] = fmaf(p, v0.w, acc[i][3]);
                acc[i][4] = fmaf(p, v1.x, acc[i][4]);
                acc[i][5] = fmaf(p, v1.y, acc[i][5]);
                acc[i][6] = fmaf(p, v1.z, acc[i][6]);
                acc[i][7] = fmaf(p, v1.w, acc[i][7]);
            }
        }
        __syncthreads();   // barrier C: all V (and Ps) reads done

        // prefetch V(t+1) — overlaps with next score stage
        if (t + 1 < nk) {
            load_v_async(vmain, rowbase, h, (t + 1) * KTILE, Vs, tid);
            asm volatile("cp.async.commit_group;\n" ::: "memory");
        }
    }

    // ---- write O, packed as [b, s, h, d] ----
#pragma unroll
    for (int i = 0; i < 4; i++) {
        float inv = 1.0f / li[i];
        long row = rowbase + m0 + r0 + i;
        float4 o0 = make_float4(acc[i][0] * inv, acc[i][1] * inv,
                                acc[i][2] * inv, acc[i][3] * inv);
        float4 o1 = make_float4(acc[i][4] * inv, acc[i][5] * inv,
                                acc[i][6] * inv, acc[i][7] * inv);
        *(float4*)&outp[row * DMODEL + h * HD + tx * 4]      = o0;
        *(float4*)&outp[row * DMODEL + h * HD + 64 + tx * 4] = o1;
    }
}

// ======================= launch ============================================
extern "C" void kernel_launch(void* const* d_in, const int* in_sizes, int n_in,
                              void* d_out, int out_size)
{
    const float* x      = (const float*)d_in[0];
    const float* w_qkv  = (const float*)d_in[1];
    const float* b_qkv  = (const float*)d_in[2];
    const float* w_qup  = (const float*)d_in[3];
    const float* b_qup  = (const float*)d_in[4];
    const float* w_kup  = (const float*)d_in[5];
    const float* b_kup  = (const float*)d_in[6];
    const float* w_vup  = (const float*)d_in[7];
    const float* b_vup  = (const float*)d_in[8];
    const float* w_qpos = (const float*)d_in[9];
    const float* b_qpos = (const float*)d_in[10];
    const float* w_kpos = (const float*)d_in[11];
    const float* b_kpos = (const float*)d_in[12];
    const float* w_o    = (const float*)d_in[13];
    const float* b_o    = (const float*)d_in[14];
    float* out = (float*)d_out;

    float *latent, *qmain, *kmain, *vmain, *posq, *posk, *attnb;
    cudaGetSymbolAddress((void**)&latent, g_latent);
    cudaGetSymbolAddress((void**)&qmain,  g_qmain);
    cudaGetSymbolAddress((void**)&kmain,  g_kmain);
    cudaGetSymbolAddress((void**)&vmain,  g_vmain);
    cudaGetSymbolAddress((void**)&posq,   g_posq);
    cudaGetSymbolAddress((void**)&posk,   g_posk);
    cudaGetSymbolAddress((void**)&attnb,  g_attn);

    cudaFuncSetAttribute(attn_kernel,
                         cudaFuncAttributeMaxDynamicSharedMemorySize,
                         ATTN_SMEM_BYTES);

    dim3 blk(256);
    const int MG = MROWS / 128;  // 32 grid rows

    // 1) latent_qkv = x @ w_qkv + b_qkv             [4096,1536]
    sgemm_bias<<<dim3(1536 / 128, MG), blk>>>(x, DMODEL, 0, w_qkv, 3 * LAT,
                                              b_qkv, latent, 3 * LAT,
                                              3 * LAT, DMODEL);
    // 2) pos_k raw = x @ w_kpos + b_kpos            [4096,64]
    sgemm_bias<<<dim3(1, MG), blk>>>(x, DMODEL, 0, w_kpos, PHD,
                                     b_kpos, posk, PHD, PHD, DMODEL);
    // 3) q/k/v up-projections in one launch         3 x [4096,2048]
    sgemm_up3<<<dim3(DMODEL / 128, MG, 3), blk>>>(latent,
                                                  w_qup, b_qup, qmain,
                                                  w_kup, b_kup, kmain,
                                                  w_vup, b_vup, vmain);
    // 4) pos_q raw = lq @ w_qpos + b_qpos           [4096,1024]
    sgemm_bias<<<dim3(1024 / 128, MG), blk>>>(latent, 3 * LAT, 0, w_qpos, NHD * PHD,
                                              b_qpos, posq, NHD * PHD, NHD * PHD, LAT);
    // 5) RoPE (in place, fused q+k)
    rope_kernel<<<(QROT + KROT + 255) / 256, 256>>>(posq, posk);

    // 6) attention -> attnb packed [b, s, h, d]
    attn_kernel<<<dim3(SS / QTILE, BB * NHD), dim3(512), ATTN_SMEM_BYTES>>>(
        qmain, posq, kmain, posk, vmain, attnb);

    // 7) out = attnb @ w_o + b_o                    [4096,2048]
    sgemm_bias<<<dim3(DMODEL / 128, MG), blk>>>(attnb, DMODEL, 0, w_o, DMODEL,
                                                b_o, out, DMODEL, DMODEL, DMODEL);
}